// round 1
// baseline (speedup 1.0000x reference)
#include <cuda_runtime.h>
#include <math.h>
#include <float.h>
#include <stdint.h>

// Problem constants
#define BB 2
#define NN 2048
#define CC 512
#define HH 8
#define DD 64
#define FF 1536   // 3*H*D

// ---------------- scratch (device globals: allocation-free) ----------------
__device__ float g_q[BB * HH * NN * DD];        // 8 MB
__device__ float g_k[BB * HH * NN * DD];        // 8 MB
__device__ float g_v[BB * HH * NN * DD];        // 8 MB
__device__ float g_dots[(size_t)BB * HH * NN * NN];   // 256 MiB
__device__ float g_attn2[(size_t)BB * HH * NN * NN];  // 256 MiB
__device__ float g_outf[BB * NN * (HH * DD)];   // 8 MB

// ---------------- shared 128x128x16 NT SGEMM core (C = A * B^T) ------------
// A: [M,K] row-major (lda), B: [N,K] row-major (ldb). 256 threads, 8x8 micro.
__device__ __forceinline__ void sgemm_nt_128(const float* __restrict__ A, int lda,
                                             const float* __restrict__ B, int ldb,
                                             int m0, int n0, int K,
                                             float (&acc)[8][8])
{
    __shared__ float As[16][132];
    __shared__ float Bs[16][132];
    const int tid = threadIdx.x;
    const int tx = tid & 15;
    const int ty = tid >> 4;
    for (int k0 = 0; k0 < K; k0 += 16) {
#pragma unroll
        for (int l = 0; l < 2; ++l) {
            int vv = tid + l * 256;          // float4 id 0..511
            int r  = vv >> 2;                // tile row 0..127
            int c4 = (vv & 3) << 2;          // k sub-col {0,4,8,12}
            float4 a4 = *(const float4*)(A + (size_t)(m0 + r) * lda + (k0 + c4));
            As[c4 + 0][r] = a4.x; As[c4 + 1][r] = a4.y;
            As[c4 + 2][r] = a4.z; As[c4 + 3][r] = a4.w;
            float4 b4 = *(const float4*)(B + (size_t)(n0 + r) * ldb + (k0 + c4));
            Bs[c4 + 0][r] = b4.x; Bs[c4 + 1][r] = b4.y;
            Bs[c4 + 2][r] = b4.z; Bs[c4 + 3][r] = b4.w;
        }
        __syncthreads();
#pragma unroll
        for (int kk = 0; kk < 16; ++kk) {
            float4 a0 = *(const float4*)&As[kk][ty * 8];
            float4 a1 = *(const float4*)&As[kk][ty * 8 + 4];
            float4 b0 = *(const float4*)&Bs[kk][tx * 8];
            float4 b1 = *(const float4*)&Bs[kk][tx * 8 + 4];
            float a[8] = {a0.x, a0.y, a0.z, a0.w, a1.x, a1.y, a1.z, a1.w};
            float b[8] = {b0.x, b0.y, b0.z, b0.w, b1.x, b1.y, b1.z, b1.w};
#pragma unroll
            for (int i = 0; i < 8; ++i)
#pragma unroll
                for (int j = 0; j < 8; ++j)
                    acc[i][j] = fmaf(a[i], b[j], acc[i][j]);
        }
        __syncthreads();
    }
}

// ---------------- K1: QKV projection + scatter into q/k/v -------------------
// proj[m,f] = sum_c x[m,c]*Wqkv[f,c];  f = h*192 + d*3 + s  (s: 0=q,1=k,2=v)
__global__ void qkv_kernel(const float* __restrict__ X, const float* __restrict__ W,
                           float* __restrict__ Q, float* __restrict__ Kp,
                           float* __restrict__ V)
{
    const int m0 = blockIdx.y * 128;
    const int n0 = blockIdx.x * 128;
    float acc[8][8] = {};
    sgemm_nt_128(X, CC, W, CC, m0, n0, CC, acc);
    const int tx = threadIdx.x & 15, ty = threadIdx.x >> 4;
#pragma unroll
    for (int ii = 0; ii < 8; ++ii) {
        int m = m0 + ty * 8 + ii;
        int b = m >> 11;          // /2048
        int n = m & 2047;
#pragma unroll
        for (int jj = 0; jj < 8; ++jj) {
            int f = n0 + tx * 8 + jj;
            int h = f / 192;
            int r = f - h * 192;
            int d = r / 3;
            int s = r - d * 3;
            size_t idx = ((((size_t)b * HH + h) * NN) + n) * DD + d;
            float val = acc[ii][jj];
            if (s == 0)      Q[idx]  = val;
            else if (s == 1) Kp[idx] = val;
            else             V[idx]  = val;
        }
    }
}

// ---------------- K2: dots = scale * q @ k^T per (b,h) ----------------------
__global__ void dots_kernel(const float* __restrict__ Q, const float* __restrict__ Kp,
                            float* __restrict__ Dots)
{
    const int bh = blockIdx.z;
    const float* A = Q  + (size_t)bh * NN * DD;
    const float* B = Kp + (size_t)bh * NN * DD;
    float* C = Dots + (size_t)bh * NN * NN;
    const int m0 = blockIdx.y * 128;
    const int n0 = blockIdx.x * 128;
    float acc[8][8] = {};
    sgemm_nt_128(A, DD, B, DD, m0, n0, DD, acc);
    const int tx = threadIdx.x & 15, ty = threadIdx.x >> 4;
    const float scale = 0.125f;  // 64^-0.5
#pragma unroll
    for (int ii = 0; ii < 8; ++ii) {
        float* row = C + (size_t)(m0 + ty * 8 + ii) * NN + n0 + tx * 8;
        float4 v0 = make_float4(acc[ii][0]*scale, acc[ii][1]*scale, acc[ii][2]*scale, acc[ii][3]*scale);
        float4 v1 = make_float4(acc[ii][4]*scale, acc[ii][5]*scale, acc[ii][6]*scale, acc[ii][7]*scale);
        *(float4*)row       = v0;
        *(float4*)(row + 4) = v1;
    }
}

// ---------------- K3: fused pre-mix + pos_bias + mask + softmax + post-mix --
// one CTA per (i, b); 8 heads * 2048 cols in SMEM (64 KB dynamic)
__global__ void mix_softmax_kernel(const float* __restrict__ Dots,
                                   const float* __restrict__ Pos,
                                   const unsigned char* __restrict__ Mask,
                                   const float* __restrict__ Wpre,
                                   const float* __restrict__ Bpre,
                                   const float* __restrict__ Wpost,
                                   const float* __restrict__ Bpost,
                                   float* __restrict__ Attn2)
{
    extern __shared__ float S[];   // [8][2048]
    __shared__ float wpre_s[64], wpost_s[64], bpre_s[8], bpost_s[8];
    __shared__ float wred[8][8];
    __shared__ float gstat[8];
    const int i = blockIdx.x;
    const int b = blockIdx.y;
    const int t = threadIdx.x;
    if (t < 64) { wpre_s[t] = Wpre[t]; wpost_s[t] = Wpost[t]; }
    if (t >= 64 && t < 72) { bpre_s[t - 64] = Bpre[t - 64]; bpost_s[t - 64] = Bpost[t - 64]; }

    // load dots rows for all 8 heads
#pragma unroll
    for (int h = 0; h < 8; ++h) {
        const float* src = Dots + (((size_t)b * HH + h) * NN + i) * NN;
#pragma unroll
        for (int c = 0; c < 8; ++c) S[h * NN + t + c * 256] = src[t + c * 256];
    }
    __syncthreads();

    float lmax[8];
#pragma unroll
    for (int g = 0; g < 8; ++g) lmax[g] = -FLT_MAX;
    const unsigned char* mrow = Mask + ((size_t)b * NN + i) * NN;

    // pre talking-heads mix + bias + pos_bias + mask (in place, column-owned)
#pragma unroll
    for (int c = 0; c < 8; ++c) {
        int j = t + c * 256;
        float sv[8];
#pragma unroll
        for (int h = 0; h < 8; ++h) sv[h] = S[h * NN + j];
        bool mk = mrow[j] != 0;
#pragma unroll
        for (int g = 0; g < 8; ++g) {
            float val = bpre_s[g];
#pragma unroll
            for (int h = 0; h < 8; ++h) val = fmaf(wpre_s[g * 8 + h], sv[h], val);
            val += Pos[((size_t)g * NN + i) * NN + j];
            if (mk) val = -FLT_MAX;
            S[g * NN + j] = val;
            lmax[g] = fmaxf(lmax[g], val);
        }
    }
    // block-reduce max per g
    const int lane = t & 31, warp = t >> 5;
#pragma unroll
    for (int g = 0; g < 8; ++g) {
        float m = lmax[g];
#pragma unroll
        for (int o = 16; o > 0; o >>= 1) m = fmaxf(m, __shfl_xor_sync(0xffffffffu, m, o));
        if (lane == 0) wred[g][warp] = m;
    }
    __syncthreads();
    if (t < 8) {
        float m = wred[t][0];
#pragma unroll
        for (int w = 1; w < 8; ++w) m = fmaxf(m, wred[t][w]);
        gstat[t] = m;
    }
    __syncthreads();
    float gmaxr[8];
#pragma unroll
    for (int g = 0; g < 8; ++g) gmaxr[g] = gstat[g];

    // exp and local sums
    float lsum[8] = {};
#pragma unroll
    for (int c = 0; c < 8; ++c) {
        int j = t + c * 256;
#pragma unroll
        for (int g = 0; g < 8; ++g) {
            float e = __expf(S[g * NN + j] - gmaxr[g]);
            S[g * NN + j] = e;
            lsum[g] += e;
        }
    }
#pragma unroll
    for (int g = 0; g < 8; ++g) {
        float s = lsum[g];
#pragma unroll
        for (int o = 16; o > 0; o >>= 1) s += __shfl_xor_sync(0xffffffffu, s, o);
        if (lane == 0) wred[g][warp] = s;
    }
    __syncthreads();
    if (t < 8) {
        float s = 0.f;
#pragma unroll
        for (int w = 0; w < 8; ++w) s += wred[t][w];
        gstat[t] = 1.0f / s;
    }
    __syncthreads();
    float inv[8];
#pragma unroll
    for (int h = 0; h < 8; ++h) inv[h] = gstat[h];

    // post talking-heads mix + bias; write attn2
#pragma unroll
    for (int c = 0; c < 8; ++c) {
        int j = t + c * 256;
        float p[8];
#pragma unroll
        for (int h = 0; h < 8; ++h) p[h] = S[h * NN + j] * inv[h];
#pragma unroll
        for (int g = 0; g < 8; ++g) {
            float o = bpost_s[g];
#pragma unroll
            for (int h = 0; h < 8; ++h) o = fmaf(wpost_s[g * 8 + h], p[h], o);
            Attn2[(((size_t)b * HH + g) * NN + i) * NN + j] = o;
        }
    }
}

// ---------------- K4: out = attn2 @ v, write [b, i, g*64+d] -----------------
__global__ void av_kernel(const float* __restrict__ Attn, const float* __restrict__ V,
                          float* __restrict__ OutF)
{
    __shared__ float As[16][132];
    __shared__ float Bs[16][64];
    const int bg = blockIdx.z;
    const int b = bg >> 3, g = bg & 7;
    const float* A  = Attn + (size_t)bg * NN * NN;
    const float* Bv = V    + (size_t)bg * NN * DD;
    const int m0 = blockIdx.y * 128;
    const int tid = threadIdx.x;
    const int tx = tid & 15;   // d group: tx*4
    const int ty = tid >> 4;   // m group: ty*8
    float acc[8][4] = {};
    for (int k0 = 0; k0 < NN; k0 += 16) {
#pragma unroll
        for (int l = 0; l < 2; ++l) {
            int vv = tid + l * 256;
            int r  = vv >> 2;
            int c4 = (vv & 3) << 2;
            float4 a4 = *(const float4*)(A + (size_t)(m0 + r) * NN + (k0 + c4));
            As[c4 + 0][r] = a4.x; As[c4 + 1][r] = a4.y;
            As[c4 + 2][r] = a4.z; As[c4 + 3][r] = a4.w;
        }
        {
            int kr = tid >> 4;
            int n4 = (tid & 15) << 2;
            float4 b4 = *(const float4*)(Bv + (size_t)(k0 + kr) * DD + n4);
            Bs[kr][n4 + 0] = b4.x; Bs[kr][n4 + 1] = b4.y;
            Bs[kr][n4 + 2] = b4.z; Bs[kr][n4 + 3] = b4.w;
        }
        __syncthreads();
#pragma unroll
        for (int kk = 0; kk < 16; ++kk) {
            float4 a0 = *(const float4*)&As[kk][ty * 8];
            float4 a1 = *(const float4*)&As[kk][ty * 8 + 4];
            float4 bb = *(const float4*)&Bs[kk][tx * 4];
            float a[8] = {a0.x, a0.y, a0.z, a0.w, a1.x, a1.y, a1.z, a1.w};
            float bf[4] = {bb.x, bb.y, bb.z, bb.w};
#pragma unroll
            for (int i2 = 0; i2 < 8; ++i2)
#pragma unroll
                for (int j2 = 0; j2 < 4; ++j2)
                    acc[i2][j2] = fmaf(a[i2], bf[j2], acc[i2][j2]);
        }
        __syncthreads();
    }
#pragma unroll
    for (int i2 = 0; i2 < 8; ++i2) {
        int m = m0 + ty * 8 + i2;
        float* dst = OutF + ((size_t)b * NN + m) * (HH * DD) + g * DD + tx * 4;
        *(float4*)dst = make_float4(acc[i2][0], acc[i2][1], acc[i2][2], acc[i2][3]);
    }
}

// ---------------- K5: final projection y = outf @ Wout^T --------------------
__global__ void out_kernel(const float* __restrict__ OutF, const float* __restrict__ W,
                           float* __restrict__ Y)
{
    const int m0 = blockIdx.y * 128;
    const int n0 = blockIdx.x * 128;
    float acc[8][8] = {};
    sgemm_nt_128(OutF, HH * DD, W, HH * DD, m0, n0, HH * DD, acc);
    const int tx = threadIdx.x & 15, ty = threadIdx.x >> 4;
#pragma unroll
    for (int ii = 0; ii < 8; ++ii) {
        float* row = Y + (size_t)(m0 + ty * 8 + ii) * CC + n0 + tx * 8;
        *(float4*)row       = make_float4(acc[ii][0], acc[ii][1], acc[ii][2], acc[ii][3]);
        *(float4*)(row + 4) = make_float4(acc[ii][4], acc[ii][5], acc[ii][6], acc[ii][7]);
    }
}

// ---------------- launch -----------------------------------------------------
extern "C" void kernel_launch(void* const* d_in, const int* in_sizes, int n_in,
                              void* d_out, int out_size)
{
    (void)in_sizes; (void)n_in; (void)out_size;
    const float*         x     = (const float*)d_in[0];
    const float*         pos   = (const float*)d_in[1];
    const unsigned char* mask  = (const unsigned char*)d_in[2];
    const float*         Wqkv  = (const float*)d_in[3];
    const float*         Wout  = (const float*)d_in[4];
    const float*         Wpre  = (const float*)d_in[5];
    const float*         bpre  = (const float*)d_in[6];
    const float*         Wpost = (const float*)d_in[7];
    const float*         bpost = (const float*)d_in[8];
    float* y = (float*)d_out;

    float *q, *k, *v, *dots, *attn2, *outf;
    cudaGetSymbolAddress((void**)&q,     g_q);
    cudaGetSymbolAddress((void**)&k,     g_k);
    cudaGetSymbolAddress((void**)&v,     g_v);
    cudaGetSymbolAddress((void**)&dots,  g_dots);
    cudaGetSymbolAddress((void**)&attn2, g_attn2);
    cudaGetSymbolAddress((void**)&outf,  g_outf);

    cudaFuncSetAttribute(mix_softmax_kernel,
                         cudaFuncAttributeMaxDynamicSharedMemorySize, 8 * NN * 4);

    qkv_kernel<<<dim3(FF / 128, (BB * NN) / 128), 256>>>(x, Wqkv, q, k, v);
    dots_kernel<<<dim3(NN / 128, NN / 128, BB * HH), 256>>>(q, k, dots);
    mix_softmax_kernel<<<dim3(NN, BB), 256, 8 * NN * 4>>>(dots, pos, mask, Wpre, bpre,
                                                          Wpost, bpost, attn2);
    av_kernel<<<dim3(1, NN / 128, BB * HH), 256>>>(attn2, v, outf);
    out_kernel<<<dim3(CC / 128, (BB * NN) / 128), 256>>>(outf, Wout, y);
}

// round 4
// speedup vs baseline: 1.2457x; 1.2457x over previous
#include <cuda_runtime.h>
#include <cuda_bf16.h>
#include <math.h>
#include <float.h>
#include <stdint.h>

// Problem constants
#define BB 2
#define NN 2048
#define CC 512
#define HH 8
#define DD 64
#define FF 1536   // 3*H*D

// ==================== scratch (device globals) ====================
__device__ float g_q[BB * HH * NN * DD];
__device__ float g_k[BB * HH * NN * DD];
__device__ float g_v[BB * HH * NN * DD];
__device__ float g_dots[(size_t)BB * HH * NN * NN];            // 256 MiB
__device__ __align__(256) __nv_bfloat16 g_qs_hi[BB * HH * NN * DD];
__device__ __align__(256) __nv_bfloat16 g_qs_lo[BB * HH * NN * DD];
__device__ __align__(256) __nv_bfloat16 g_ks_hi[BB * HH * NN * DD];
__device__ __align__(256) __nv_bfloat16 g_ks_lo[BB * HH * NN * DD];
__device__ __align__(256) __nv_bfloat16 g_vt_hi[BB * HH * DD * NN];   // [bh][d][n]
__device__ __align__(256) __nv_bfloat16 g_vt_lo[BB * HH * DD * NN];
__device__ __align__(256) __nv_bfloat16 g_attn_hi[(size_t)BB * HH * NN * NN]; // 128 MiB
__device__ __align__(256) __nv_bfloat16 g_attn_lo[(size_t)BB * HH * NN * NN]; // 128 MiB
__device__ float g_outf[BB * NN * (HH * DD)];

// ==================== mma.sync helpers (sm_80+ path) ====================
__device__ __forceinline__ uint32_t smem_u32(const void* p) {
    uint32_t a;
    asm("{ .reg .u64 t; cvta.to.shared.u64 t, %1; cvt.u32.u64 %0, t; }" : "=r"(a) : "l"(p));
    return a;
}
__device__ __forceinline__ uint32_t sw128(uint32_t off) { return off ^ ((off >> 3) & 0x70); }

__device__ __forceinline__ void ldsm4(uint32_t (&r)[4], uint32_t addr) {
    asm volatile("ldmatrix.sync.aligned.m8n8.x4.shared.b16 {%0,%1,%2,%3}, [%4];"
        : "=r"(r[0]), "=r"(r[1]), "=r"(r[2]), "=r"(r[3]) : "r"(addr));
}
__device__ __forceinline__ void mma16816(float (&c)[4], const uint32_t (&a)[4],
                                         uint32_t b0, uint32_t b1) {
    asm volatile("mma.sync.aligned.m16n8k16.row.col.f32.bf16.bf16.f32 "
        "{%0,%1,%2,%3}, {%4,%5,%6,%7}, {%8,%9}, {%0,%1,%2,%3};"
        : "+f"(c[0]), "+f"(c[1]), "+f"(c[2]), "+f"(c[3])
        : "r"(a[0]), "r"(a[1]), "r"(a[2]), "r"(a[3]), "r"(b0), "r"(b1));
}

// ==================== fp32 SGEMM core (qkv / out projections) ====================
__device__ __forceinline__ void sgemm_nt_128(const float* __restrict__ A, int lda,
                                             const float* __restrict__ B, int ldb,
                                             int m0, int n0, int K,
                                             float (&acc)[8][8])
{
    __shared__ float As[16][132];
    __shared__ float Bs[16][132];
    const int tid = threadIdx.x;
    const int tx = tid & 15;
    const int ty = tid >> 4;
    for (int k0 = 0; k0 < K; k0 += 16) {
#pragma unroll
        for (int l = 0; l < 2; ++l) {
            int vv = tid + l * 256;
            int r  = vv >> 2;
            int c4 = (vv & 3) << 2;
            float4 a4 = *(const float4*)(A + (size_t)(m0 + r) * lda + (k0 + c4));
            As[c4 + 0][r] = a4.x; As[c4 + 1][r] = a4.y;
            As[c4 + 2][r] = a4.z; As[c4 + 3][r] = a4.w;
            float4 b4 = *(const float4*)(B + (size_t)(n0 + r) * ldb + (k0 + c4));
            Bs[c4 + 0][r] = b4.x; Bs[c4 + 1][r] = b4.y;
            Bs[c4 + 2][r] = b4.z; Bs[c4 + 3][r] = b4.w;
        }
        __syncthreads();
#pragma unroll
        for (int kk = 0; kk < 16; ++kk) {
            float4 a0 = *(const float4*)&As[kk][ty * 8];
            float4 a1 = *(const float4*)&As[kk][ty * 8 + 4];
            float4 b0 = *(const float4*)&Bs[kk][tx * 8];
            float4 b1 = *(const float4*)&Bs[kk][tx * 8 + 4];
            float a[8] = {a0.x, a0.y, a0.z, a0.w, a1.x, a1.y, a1.z, a1.w};
            float b[8] = {b0.x, b0.y, b0.z, b0.w, b1.x, b1.y, b1.z, b1.w};
#pragma unroll
            for (int i = 0; i < 8; ++i)
#pragma unroll
                for (int j = 0; j < 8; ++j)
                    acc[i][j] = fmaf(a[i], b[j], acc[i][j]);
        }
        __syncthreads();
    }
}

// ---------------- K1: QKV projection + scatter ----------------
__global__ void qkv_kernel(const float* __restrict__ X, const float* __restrict__ W,
                           float* __restrict__ Q, float* __restrict__ Kp,
                           float* __restrict__ V)
{
    const int m0 = blockIdx.y * 128;
    const int n0 = blockIdx.x * 128;
    float acc[8][8] = {};
    sgemm_nt_128(X, CC, W, CC, m0, n0, CC, acc);
    const int tx = threadIdx.x & 15, ty = threadIdx.x >> 4;
#pragma unroll
    for (int ii = 0; ii < 8; ++ii) {
        int m = m0 + ty * 8 + ii;
        int b = m >> 11;
        int n = m & 2047;
#pragma unroll
        for (int jj = 0; jj < 8; ++jj) {
            int f = n0 + tx * 8 + jj;
            int h = f / 192;
            int r = f - h * 192;
            int d = r / 3;
            int s = r - d * 3;
            size_t idx = ((((size_t)b * HH + h) * NN) + n) * DD + d;
            float val = acc[ii][jj];
            if (s == 0)      Q[idx]  = val;
            else if (s == 1) Kp[idx] = val;
            else             V[idx]  = val;
        }
    }
}

// ---------------- K1b: split fp32 -> bf16 hi/lo (+ scale q, transpose v) -----
__global__ void convert_kernel(const float* __restrict__ Q, const float* __restrict__ Kp,
                               const float* __restrict__ V,
                               __nv_bfloat16* __restrict__ QH, __nv_bfloat16* __restrict__ QL,
                               __nv_bfloat16* __restrict__ KH, __nv_bfloat16* __restrict__ KL,
                               __nv_bfloat16* __restrict__ VTH, __nv_bfloat16* __restrict__ VTL)
{
    __shared__ float ts[64][65];
    const int bh = blockIdx.y;
    const int n0 = blockIdx.x * 64;
    const int t = threadIdx.x;
    const size_t base = ((size_t)bh * NN + n0) * DD;
    for (int idx = t; idx < 64 * 64; idx += 256) {
        float qv = Q[base + idx] * 0.125f;   // fold 1/sqrt(64), exact power of two
        __nv_bfloat16 qh = __float2bfloat16(qv);
        QH[base + idx] = qh;
        QL[base + idx] = __float2bfloat16(qv - __bfloat162float(qh));
        float kv = Kp[base + idx];
        __nv_bfloat16 kh = __float2bfloat16(kv);
        KH[base + idx] = kh;
        KL[base + idx] = __float2bfloat16(kv - __bfloat162float(kh));
        ts[idx >> 6][idx & 63] = V[base + idx];
    }
    __syncthreads();
    for (int idx = t; idx < 64 * 64; idx += 256) {
        int d = idx >> 6, c = idx & 63;
        float vv = ts[c][d];
        __nv_bfloat16 vh = __float2bfloat16(vv);
        size_t o = ((size_t)bh * DD + d) * NN + n0 + c;
        VTH[o] = vh;
        VTL[o] = __float2bfloat16(vv - __bfloat162float(vh));
    }
}

// ---------------- K2: dots = (q_hi+lo)(k_hi+lo)^T via mma.sync --------------
#define DK_AH 0
#define DK_AL 16384
#define DK_BH 32768
#define DK_BL 49152
#define DK_SMEM 65536

__global__ __launch_bounds__(256)
void dots_mma_kernel(const __nv_bfloat16* __restrict__ QH, const __nv_bfloat16* __restrict__ QL,
                     const __nv_bfloat16* __restrict__ KH, const __nv_bfloat16* __restrict__ KL,
                     float* __restrict__ Dots)
{
    extern __shared__ __align__(128) char smem[];
    const uint32_t sb = smem_u32(smem);
    const int t = threadIdx.x;
    const int lane = t & 31, warp = t >> 5;
    const int wm = (warp & 3) * 32;      // warp row offset in 128
    const int wn = (warp >> 2) * 64;     // warp col offset in 128
    const int bh = blockIdx.z;
    const int m0 = blockIdx.y * 128;
    const int n0 = blockIdx.x * 128;

    // load 4 tiles, each 128 rows x 64 bf16 = 128 bytes/row = 8 uint4 chunks/row
    const __nv_bfloat16* qh = QH + ((size_t)bh * NN + m0) * DD;
    const __nv_bfloat16* ql = QL + ((size_t)bh * NN + m0) * DD;
    const __nv_bfloat16* kh = KH + ((size_t)bh * NN + n0) * DD;
    const __nv_bfloat16* kl = KL + ((size_t)bh * NN + n0) * DD;
#pragma unroll
    for (int rep = 0; rep < 4; ++rep) {
        int idx = t + rep * 256;           // 1024 16B-chunks per tile
        int r = idx >> 3, c8 = idx & 7;
        uint32_t off = sw128(r * 128 + c8 * 16);
        int go = r * DD + c8 * 8;
        *(uint4*)(smem + DK_AH + off) = *(const uint4*)(qh + go);
        *(uint4*)(smem + DK_AL + off) = *(const uint4*)(ql + go);
        *(uint4*)(smem + DK_BH + off) = *(const uint4*)(kh + go);
        *(uint4*)(smem + DK_BL + off) = *(const uint4*)(kl + go);
    }
    __syncthreads();

    float acc[2][8][4] = {};
    const uint32_t aoffs[3] = {DK_AH, DK_AH, DK_AL};
    const uint32_t boffs[3] = {DK_BH, DK_BL, DK_BH};
#pragma unroll
    for (int c3 = 0; c3 < 3; ++c3) {
        const uint32_t abase = sb + aoffs[c3];
        const uint32_t bbase = sb + boffs[c3];
#pragma unroll
        for (int ks = 0; ks < 4; ++ks) {
            uint32_t a[2][4];
#pragma unroll
            for (int mt = 0; mt < 2; ++mt) {
                uint32_t row = wm + mt * 16 + (lane & 15);
                uint32_t addr = abase + sw128(row * 128 + ks * 32 + (lane >> 4) * 16);
                ldsm4(a[mt], addr);
            }
            uint32_t bf[4][4];
#pragma unroll
            for (int np = 0; np < 4; ++np) {
                uint32_t row = wn + np * 16 + (lane & 7) + ((lane >> 4) << 3);
                uint32_t addr = bbase + sw128(row * 128 + ks * 32 + ((lane >> 3) & 1) * 16);
                ldsm4(bf[np], addr);
            }
#pragma unroll
            for (int mt = 0; mt < 2; ++mt)
#pragma unroll
                for (int nt = 0; nt < 8; ++nt)
                    mma16816(acc[mt][nt], a[mt], bf[nt >> 1][(nt & 1) * 2], bf[nt >> 1][(nt & 1) * 2 + 1]);
        }
    }

    // epilogue: direct float2 stores
    float* C = Dots + ((size_t)bh * NN + m0) * NN + n0;
#pragma unroll
    for (int mt = 0; mt < 2; ++mt) {
        int row = wm + mt * 16 + (lane >> 2);
#pragma unroll
        for (int nt = 0; nt < 8; ++nt) {
            int col = wn + nt * 8 + (lane & 3) * 2;
            *(float2*)(C + (size_t)row * NN + col)       = make_float2(acc[mt][nt][0], acc[mt][nt][1]);
            *(float2*)(C + (size_t)(row + 8) * NN + col) = make_float2(acc[mt][nt][2], acc[mt][nt][3]);
        }
    }
}

// ---------------- K3: fused pre-mix + pos_bias + mask + softmax + post-mix --
__global__ void mix_softmax_kernel(const float* __restrict__ Dots,
                                   const float* __restrict__ Pos,
                                   const unsigned char* __restrict__ Mask,
                                   const float* __restrict__ Wpre,
                                   const float* __restrict__ Bpre,
                                   const float* __restrict__ Wpost,
                                   const float* __restrict__ Bpost,
                                   __nv_bfloat16* __restrict__ AttnHi,
                                   __nv_bfloat16* __restrict__ AttnLo)
{
    extern __shared__ float S[];   // [8][2048]
    __shared__ float wpre_s[64], wpost_s[64], bpre_s[8], bpost_s[8];
    __shared__ float wred[8][8];
    __shared__ float gstat[8];
    const int i = blockIdx.x;
    const int b = blockIdx.y;
    const int t = threadIdx.x;
    if (t < 64) { wpre_s[t] = Wpre[t]; wpost_s[t] = Wpost[t]; }
    if (t >= 64 && t < 72) { bpre_s[t - 64] = Bpre[t - 64]; bpost_s[t - 64] = Bpost[t - 64]; }

#pragma unroll
    for (int h = 0; h < 8; ++h) {
        const float* src = Dots + (((size_t)b * HH + h) * NN + i) * NN;
#pragma unroll
        for (int c = 0; c < 8; ++c) S[h * NN + t + c * 256] = src[t + c * 256];
    }
    __syncthreads();

    float lmax[8];
#pragma unroll
    for (int g = 0; g < 8; ++g) lmax[g] = -FLT_MAX;
    const unsigned char* mrow = Mask + ((size_t)b * NN + i) * NN;

#pragma unroll
    for (int c = 0; c < 8; ++c) {
        int j = t + c * 256;
        float sv[8];
#pragma unroll
        for (int h = 0; h < 8; ++h) sv[h] = S[h * NN + j];
        bool mk = mrow[j] != 0;
#pragma unroll
        for (int g = 0; g < 8; ++g) {
            float val = bpre_s[g];
#pragma unroll
            for (int h = 0; h < 8; ++h) val = fmaf(wpre_s[g * 8 + h], sv[h], val);
            val += Pos[((size_t)g * NN + i) * NN + j];
            if (mk) val = -FLT_MAX;
            S[g * NN + j] = val;
            lmax[g] = fmaxf(lmax[g], val);
        }
    }
    const int lane = t & 31, warp = t >> 5;
#pragma unroll
    for (int g = 0; g < 8; ++g) {
        float m = lmax[g];
#pragma unroll
        for (int o = 16; o > 0; o >>= 1) m = fmaxf(m, __shfl_xor_sync(0xffffffffu, m, o));
        if (lane == 0) wred[g][warp] = m;
    }
    __syncthreads();
    if (t < 8) {
        float m = wred[t][0];
#pragma unroll
        for (int w = 1; w < 8; ++w) m = fmaxf(m, wred[t][w]);
        gstat[t] = m;
    }
    __syncthreads();
    float gmaxr[8];
#pragma unroll
    for (int g = 0; g < 8; ++g) gmaxr[g] = gstat[g];

    float lsum[8] = {};
#pragma unroll
    for (int c = 0; c < 8; ++c) {
        int j = t + c * 256;
#pragma unroll
        for (int g = 0; g < 8; ++g) {
            float e = __expf(S[g * NN + j] - gmaxr[g]);
            S[g * NN + j] = e;
            lsum[g] += e;
        }
    }
#pragma unroll
    for (int g = 0; g < 8; ++g) {
        float s = lsum[g];
#pragma unroll
        for (int o = 16; o > 0; o >>= 1) s += __shfl_xor_sync(0xffffffffu, s, o);
        if (lane == 0) wred[g][warp] = s;
    }
    __syncthreads();
    if (t < 8) {
        float s = 0.f;
#pragma unroll
        for (int w = 0; w < 8; ++w) s += wred[t][w];
        gstat[t] = 1.0f / s;
    }
    __syncthreads();
    float inv[8];
#pragma unroll
    for (int h = 0; h < 8; ++h) inv[h] = gstat[h];

#pragma unroll
    for (int c = 0; c < 8; ++c) {
        int j = t + c * 256;
        float p[8];
#pragma unroll
        for (int h = 0; h < 8; ++h) p[h] = S[h * NN + j] * inv[h];
#pragma unroll
        for (int g = 0; g < 8; ++g) {
            float o = bpost_s[g];
#pragma unroll
            for (int h = 0; h < 8; ++h) o = fmaf(wpost_s[g * 8 + h], p[h], o);
            size_t ofs = (((size_t)b * HH + g) * NN + i) * NN + j;
            __nv_bfloat16 hi = __float2bfloat16(o);
            AttnHi[ofs] = hi;
            AttnLo[ofs] = __float2bfloat16(o - __bfloat162float(hi));
        }
    }
}

// ---------------- K4: out = attn @ v via mma.sync (K-loop over j) ----------
#define AV_AH 0
#define AV_AL 16384
#define AV_BH 32768
#define AV_BL 40960
#define AV_SMEM 49152

__global__ __launch_bounds__(256)
void av_mma_kernel(const __nv_bfloat16* __restrict__ AttnHi, const __nv_bfloat16* __restrict__ AttnLo,
                   const __nv_bfloat16* __restrict__ VTH, const __nv_bfloat16* __restrict__ VTL,
                   float* __restrict__ OutF)
{
    extern __shared__ __align__(128) char smem[];
    const uint32_t sb = smem_u32(smem);
    const int t = threadIdx.x;
    const int lane = t & 31, warp = t >> 5;
    const int wm = (warp & 3) * 32;     // rows in 128
    const int wn = (warp >> 2) * 32;    // d-cols in 64
    const int bh = blockIdx.y;
    const int b = bh >> 3, h = bh & 7;
    const int m0 = blockIdx.x * 128;

    const __nv_bfloat16* Ah = AttnHi + ((size_t)bh * NN + m0) * NN;
    const __nv_bfloat16* Al = AttnLo + ((size_t)bh * NN + m0) * NN;
    const __nv_bfloat16* Vh = VTH + (size_t)bh * DD * NN;
    const __nv_bfloat16* Vl = VTL + (size_t)bh * DD * NN;

    float acc[2][4][4] = {};
    const uint32_t aoffs[3] = {AV_AH, AV_AH, AV_AL};
    const uint32_t boffs[3] = {AV_BH, AV_BL, AV_BH};

    for (int it = 0; it < 32; ++it) {
        const int j0 = it * 64;
        // attn tiles: 128 rows x 64 bf16 = 1024 chunks each
#pragma unroll
        for (int rep = 0; rep < 4; ++rep) {
            int idx = t + rep * 256;
            int r = idx >> 3, c8 = idx & 7;
            uint32_t off = sw128(r * 128 + c8 * 16);
            size_t go = (size_t)r * NN + j0 + c8 * 8;
            *(uint4*)(smem + AV_AH + off) = *(const uint4*)(Ah + go);
            *(uint4*)(smem + AV_AL + off) = *(const uint4*)(Al + go);
        }
        // v tiles: 64 rows (d) x 64 bf16 = 512 chunks each
#pragma unroll
        for (int rep = 0; rep < 2; ++rep) {
            int idx = t + rep * 256;
            int r = idx >> 3, c8 = idx & 7;
            uint32_t off = sw128(r * 128 + c8 * 16);
            size_t go = (size_t)r * NN + j0 + c8 * 8;
            *(uint4*)(smem + AV_BH + off) = *(const uint4*)(Vh + go);
            *(uint4*)(smem + AV_BL + off) = *(const uint4*)(Vl + go);
        }
        __syncthreads();
#pragma unroll
        for (int c3 = 0; c3 < 3; ++c3) {
            const uint32_t abase = sb + aoffs[c3];
            const uint32_t bbase = sb + boffs[c3];
#pragma unroll
            for (int ks = 0; ks < 4; ++ks) {
                uint32_t a[2][4];
#pragma unroll
                for (int mt = 0; mt < 2; ++mt) {
                    uint32_t row = wm + mt * 16 + (lane & 15);
                    uint32_t addr = abase + sw128(row * 128 + ks * 32 + (lane >> 4) * 16);
                    ldsm4(a[mt], addr);
                }
                uint32_t bf[2][4];
#pragma unroll
                for (int np = 0; np < 2; ++np) {
                    uint32_t row = wn + np * 16 + (lane & 7) + ((lane >> 4) << 3);
                    uint32_t addr = bbase + sw128(row * 128 + ks * 32 + ((lane >> 3) & 1) * 16);
                    ldsm4(bf[np], addr);
                }
#pragma unroll
                for (int mt = 0; mt < 2; ++mt)
#pragma unroll
                    for (int nt = 0; nt < 4; ++nt)
                        mma16816(acc[mt][nt], a[mt], bf[nt >> 1][(nt & 1) * 2], bf[nt >> 1][(nt & 1) * 2 + 1]);
            }
        }
        __syncthreads();
    }

    // epilogue: OutF[b][i][h*64+d]
#pragma unroll
    for (int mt = 0; mt < 2; ++mt) {
        int row = m0 + wm + mt * 16 + (lane >> 2);
        float* p0 = OutF + ((size_t)b * NN + row) * (HH * DD) + h * DD;
        float* p1 = OutF + ((size_t)b * NN + row + 8) * (HH * DD) + h * DD;
#pragma unroll
        for (int nt = 0; nt < 4; ++nt) {
            int col = wn + nt * 8 + (lane & 3) * 2;
            *(float2*)(p0 + col) = make_float2(acc[mt][nt][0], acc[mt][nt][1]);
            *(float2*)(p1 + col) = make_float2(acc[mt][nt][2], acc[mt][nt][3]);
        }
    }
}

// ---------------- K5: final projection y = outf @ Wout^T --------------------
__global__ void out_kernel(const float* __restrict__ OutF, const float* __restrict__ W,
                           float* __restrict__ Y)
{
    const int m0 = blockIdx.y * 128;
    const int n0 = blockIdx.x * 128;
    float acc[8][8] = {};
    sgemm_nt_128(OutF, HH * DD, W, HH * DD, m0, n0, HH * DD, acc);
    const int tx = threadIdx.x & 15, ty = threadIdx.x >> 4;
#pragma unroll
    for (int ii = 0; ii < 8; ++ii) {
        float* row = Y + (size_t)(m0 + ty * 8 + ii) * CC + n0 + tx * 8;
        *(float4*)row       = make_float4(acc[ii][0], acc[ii][1], acc[ii][2], acc[ii][3]);
        *(float4*)(row + 4) = make_float4(acc[ii][4], acc[ii][5], acc[ii][6], acc[ii][7]);
    }
}

// ---------------- launch -----------------------------------------------------
extern "C" void kernel_launch(void* const* d_in, const int* in_sizes, int n_in,
                              void* d_out, int out_size)
{
    (void)in_sizes; (void)n_in; (void)out_size;
    const float*         x     = (const float*)d_in[0];
    const float*         pos   = (const float*)d_in[1];
    const unsigned char* mask  = (const unsigned char*)d_in[2];
    const float*         Wqkv  = (const float*)d_in[3];
    const float*         Wout  = (const float*)d_in[4];
    const float*         Wpre  = (const float*)d_in[5];
    const float*         bpre  = (const float*)d_in[6];
    const float*         Wpost = (const float*)d_in[7];
    const float*         bpost = (const float*)d_in[8];
    float* y = (float*)d_out;

    float *q, *k, *v, *dots, *outf;
    __nv_bfloat16 *qh, *ql, *kh, *kl, *vth, *vtl, *ah, *al;
    cudaGetSymbolAddress((void**)&q,    g_q);
    cudaGetSymbolAddress((void**)&k,    g_k);
    cudaGetSymbolAddress((void**)&v,    g_v);
    cudaGetSymbolAddress((void**)&dots, g_dots);
    cudaGetSymbolAddress((void**)&outf, g_outf);
    cudaGetSymbolAddress((void**)&qh,  g_qs_hi);
    cudaGetSymbolAddress((void**)&ql,  g_qs_lo);
    cudaGetSymbolAddress((void**)&kh,  g_ks_hi);
    cudaGetSymbolAddress((void**)&kl,  g_ks_lo);
    cudaGetSymbolAddress((void**)&vth, g_vt_hi);
    cudaGetSymbolAddress((void**)&vtl, g_vt_lo);
    cudaGetSymbolAddress((void**)&ah,  g_attn_hi);
    cudaGetSymbolAddress((void**)&al,  g_attn_lo);

    cudaFuncSetAttribute(mix_softmax_kernel, cudaFuncAttributeMaxDynamicSharedMemorySize, 8 * NN * 4);
    cudaFuncSetAttribute(dots_mma_kernel, cudaFuncAttributeMaxDynamicSharedMemorySize, DK_SMEM);
    cudaFuncSetAttribute(av_mma_kernel, cudaFuncAttributeMaxDynamicSharedMemorySize, AV_SMEM);

    qkv_kernel<<<dim3(FF / 128, (BB * NN) / 128), 256>>>(x, Wqkv, q, k, v);
    convert_kernel<<<dim3(NN / 64, BB * HH), 256>>>(q, k, v, qh, ql, kh, kl, vth, vtl);
    dots_mma_kernel<<<dim3(NN / 128, NN / 128, BB * HH), 256, DK_SMEM>>>(qh, ql, kh, kl, dots);
    mix_softmax_kernel<<<dim3(NN, BB), 256, 8 * NN * 4>>>(dots, pos, mask, Wpre, bpre,
                                                          Wpost, bpost, ah, al);
    av_mma_kernel<<<dim3(NN / 128, BB * HH), 256, AV_SMEM>>>(ah, al, vth, vtl, outf);
    out_kernel<<<dim3(CC / 128, (BB * NN) / 128), 256>>>(outf, Wout, y);
}

// round 5
// speedup vs baseline: 1.5966x; 1.2817x over previous
#include <cuda_runtime.h>
#include <cuda_bf16.h>
#include <math.h>
#include <float.h>
#include <stdint.h>

// Problem constants
#define BB 2
#define NN 2048
#define CC 512
#define HH 8
#define DD 64
#define FF 1536   // 3*H*D

// ==================== scratch (device globals) ====================
__device__ float g_v[BB * HH * NN * DD];
__device__ float g_dots[(size_t)BB * HH * NN * NN];            // 256 MiB
__device__ __align__(256) __nv_bfloat16 g_xh[BB * NN * CC];
__device__ __align__(256) __nv_bfloat16 g_xl[BB * NN * CC];
__device__ __align__(256) __nv_bfloat16 g_wqh[FF * CC];
__device__ __align__(256) __nv_bfloat16 g_wql[FF * CC];
__device__ __align__(256) __nv_bfloat16 g_woh[CC * HH * DD];
__device__ __align__(256) __nv_bfloat16 g_wol[CC * HH * DD];
__device__ __align__(256) __nv_bfloat16 g_qs_hi[BB * HH * NN * DD];
__device__ __align__(256) __nv_bfloat16 g_qs_lo[BB * HH * NN * DD];
__device__ __align__(256) __nv_bfloat16 g_ks_hi[BB * HH * NN * DD];
__device__ __align__(256) __nv_bfloat16 g_ks_lo[BB * HH * NN * DD];
__device__ __align__(256) __nv_bfloat16 g_vt_hi[BB * HH * DD * NN];   // [bh][d][n]
__device__ __align__(256) __nv_bfloat16 g_vt_lo[BB * HH * DD * NN];
__device__ __align__(256) __nv_bfloat16 g_attn_hi[(size_t)BB * HH * NN * NN]; // 128 MiB
__device__ __align__(256) __nv_bfloat16 g_attn_lo[(size_t)BB * HH * NN * NN]; // 128 MiB
__device__ __align__(256) __nv_bfloat16 g_outf_hi[BB * NN * (HH * DD)];
__device__ __align__(256) __nv_bfloat16 g_outf_lo[BB * NN * (HH * DD)];

// ==================== mma.sync helpers ====================
__device__ __forceinline__ uint32_t smem_u32(const void* p) {
    uint32_t a;
    asm("{ .reg .u64 t; cvta.to.shared.u64 t, %1; cvt.u32.u64 %0, t; }" : "=r"(a) : "l"(p));
    return a;
}
__device__ __forceinline__ uint32_t sw128(uint32_t off) { return off ^ ((off >> 3) & 0x70); }

__device__ __forceinline__ void ldsm4(uint32_t (&r)[4], uint32_t addr) {
    asm volatile("ldmatrix.sync.aligned.m8n8.x4.shared.b16 {%0,%1,%2,%3}, [%4];"
        : "=r"(r[0]), "=r"(r[1]), "=r"(r[2]), "=r"(r[3]) : "r"(addr));
}
__device__ __forceinline__ void mma16816(float (&c)[4], const uint32_t (&a)[4],
                                         uint32_t b0, uint32_t b1) {
    asm volatile("mma.sync.aligned.m16n8k16.row.col.f32.bf16.bf16.f32 "
        "{%0,%1,%2,%3}, {%4,%5,%6,%7}, {%8,%9}, {%0,%1,%2,%3};"
        : "+f"(c[0]), "+f"(c[1]), "+f"(c[2]), "+f"(c[3])
        : "r"(a[0]), "r"(a[1]), "r"(a[2]), "r"(a[3]), "r"(b0), "r"(b1));
}

// ==================== generic split-bf16 NT MMA mainloop (128x128 tile) =======
#define GK_AH 0
#define GK_AL 16384
#define GK_BH 32768
#define GK_BL 49152
#define GK_SMEM 65536

__device__ __forceinline__ void mma_nt_mainloop(
    const __nv_bfloat16* __restrict__ AH, const __nv_bfloat16* __restrict__ AL, int lda, int m0,
    const __nv_bfloat16* __restrict__ BH, const __nv_bfloat16* __restrict__ BL, int ldb, int n0,
    int K, char* smem, uint32_t sb, float (&acc)[2][8][4])
{
    const int t = threadIdx.x, lane = t & 31, warp = t >> 5;
    const int wm = (warp & 3) * 32, wn = (warp >> 2) * 64;
    const uint32_t aoffs[3] = {GK_AH, GK_AH, GK_AL};
    const uint32_t boffs[3] = {GK_BH, GK_BL, GK_BH};
    for (int k0 = 0; k0 < K; k0 += 64) {
#pragma unroll
        for (int rep = 0; rep < 4; ++rep) {
            int idx = t + rep * 256;           // 1024 16B chunks per 128x64 tile
            int r = idx >> 3, c8 = idx & 7;
            uint32_t off = sw128(r * 128 + c8 * 16);
            size_t ga = (size_t)(m0 + r) * lda + k0 + c8 * 8;
            size_t gb = (size_t)(n0 + r) * ldb + k0 + c8 * 8;
            *(uint4*)(smem + GK_AH + off) = *(const uint4*)(AH + ga);
            *(uint4*)(smem + GK_AL + off) = *(const uint4*)(AL + ga);
            *(uint4*)(smem + GK_BH + off) = *(const uint4*)(BH + gb);
            *(uint4*)(smem + GK_BL + off) = *(const uint4*)(BL + gb);
        }
        __syncthreads();
#pragma unroll
        for (int c3 = 0; c3 < 3; ++c3) {
            const uint32_t abase = sb + aoffs[c3];
            const uint32_t bbase = sb + boffs[c3];
#pragma unroll
            for (int ks = 0; ks < 4; ++ks) {
                uint32_t a[2][4];
#pragma unroll
                for (int mt = 0; mt < 2; ++mt) {
                    uint32_t row = wm + mt * 16 + (lane & 15);
                    ldsm4(a[mt], abase + sw128(row * 128 + ks * 32 + (lane >> 4) * 16));
                }
                uint32_t bf[4][4];
#pragma unroll
                for (int np = 0; np < 4; ++np) {
                    uint32_t row = wn + np * 16 + (lane & 7) + ((lane >> 4) << 3);
                    ldsm4(bf[np], bbase + sw128(row * 128 + ks * 32 + ((lane >> 3) & 1) * 16));
                }
#pragma unroll
                for (int mt = 0; mt < 2; ++mt)
#pragma unroll
                    for (int nt = 0; nt < 8; ++nt)
                        mma16816(acc[mt][nt], a[mt], bf[nt >> 1][(nt & 1) * 2], bf[nt >> 1][(nt & 1) * 2 + 1]);
            }
        }
        __syncthreads();
    }
}

// ---------------- K0: split fp32 -> bf16 hi/lo ----------------
__global__ void split_kernel(const float* __restrict__ in, __nv_bfloat16* __restrict__ hi,
                             __nv_bfloat16* __restrict__ lo, int n)
{
    int i = blockIdx.x * 256 + threadIdx.x;
    if (i < n) {
        float v = in[i];
        __nv_bfloat16 h = __float2bfloat16(v);
        hi[i] = h;
        lo[i] = __float2bfloat16(v - __bfloat162float(h));
    }
}

// ---------------- K1: QKV projection (split-bf16 MMA) + scatter --------------
__global__ __launch_bounds__(256)
void qkv_mma_kernel(const __nv_bfloat16* __restrict__ XH, const __nv_bfloat16* __restrict__ XL,
                    const __nv_bfloat16* __restrict__ WH, const __nv_bfloat16* __restrict__ WL,
                    __nv_bfloat16* __restrict__ QH, __nv_bfloat16* __restrict__ QL,
                    __nv_bfloat16* __restrict__ KH, __nv_bfloat16* __restrict__ KL,
                    float* __restrict__ V)
{
    extern __shared__ __align__(128) char smem[];
    const uint32_t sb = smem_u32(smem);
    const int m0 = blockIdx.y * 128;
    const int n0 = blockIdx.x * 128;
    const int lane = threadIdx.x & 31, warp = threadIdx.x >> 5;
    const int wm = (warp & 3) * 32, wn = (warp >> 2) * 64;
    float acc[2][8][4] = {};
    mma_nt_mainloop(XH, XL, CC, m0, WH, WL, CC, n0, CC, smem, sb, acc);

#pragma unroll
    for (int mt = 0; mt < 2; ++mt) {
        int row0 = m0 + wm + mt * 16 + (lane >> 2);
#pragma unroll
        for (int half = 0; half < 2; ++half) {
            int m = row0 + half * 8;
            int b = m >> 11, n = m & 2047;
#pragma unroll
            for (int nt = 0; nt < 8; ++nt) {
                int f0 = n0 + wn + nt * 8 + (lane & 3) * 2;
#pragma unroll
                for (int e = 0; e < 2; ++e) {
                    int f = f0 + e;
                    float val = acc[mt][nt][half * 2 + e];
                    int h = f / 192;
                    int r = f - h * 192;
                    int d = r / 3;
                    int s = r - d * 3;
                    size_t idx = (((size_t)b * HH + h) * NN + n) * DD + d;
                    if (s == 0) {
                        float qv = val * 0.125f;
                        __nv_bfloat16 hb = __float2bfloat16(qv);
                        QH[idx] = hb;
                        QL[idx] = __float2bfloat16(qv - __bfloat162float(hb));
                    } else if (s == 1) {
                        __nv_bfloat16 hb = __float2bfloat16(val);
                        KH[idx] = hb;
                        KL[idx] = __float2bfloat16(val - __bfloat162float(hb));
                    } else {
                        V[idx] = val;
                    }
                }
            }
        }
    }
}

// ---------------- K1b: transpose V -> vt hi/lo -------------------------------
__global__ void convert_v_kernel(const float* __restrict__ V,
                                 __nv_bfloat16* __restrict__ VTH, __nv_bfloat16* __restrict__ VTL)
{
    __shared__ float ts[64][65];
    const int bh = blockIdx.y;
    const int n0 = blockIdx.x * 64;
    const int t = threadIdx.x;
    const size_t base = ((size_t)bh * NN + n0) * DD;
    for (int idx = t; idx < 64 * 64; idx += 256)
        ts[idx >> 6][idx & 63] = V[base + idx];
    __syncthreads();
    for (int idx = t; idx < 64 * 64; idx += 256) {
        int d = idx >> 6, c = idx & 63;
        float vv = ts[c][d];
        __nv_bfloat16 vh = __float2bfloat16(vv);
        size_t o = ((size_t)bh * DD + d) * NN + n0 + c;
        VTH[o] = vh;
        VTL[o] = __float2bfloat16(vv - __bfloat162float(vh));
    }
}

// ---------------- K2: dots = (q_hi+lo)(k_hi+lo)^T via mma.sync --------------
#define DK_AH 0
#define DK_AL 16384
#define DK_BH 32768
#define DK_BL 49152
#define DK_SMEM 65536

__global__ __launch_bounds__(256)
void dots_mma_kernel(const __nv_bfloat16* __restrict__ QH, const __nv_bfloat16* __restrict__ QL,
                     const __nv_bfloat16* __restrict__ KH, const __nv_bfloat16* __restrict__ KL,
                     float* __restrict__ Dots)
{
    extern __shared__ __align__(128) char smem[];
    const uint32_t sb = smem_u32(smem);
    const int t = threadIdx.x;
    const int lane = t & 31, warp = t >> 5;
    const int wm = (warp & 3) * 32;
    const int wn = (warp >> 2) * 64;
    const int bh = blockIdx.z;
    const int m0 = blockIdx.y * 128;
    const int n0 = blockIdx.x * 128;

    const __nv_bfloat16* qh = QH + ((size_t)bh * NN + m0) * DD;
    const __nv_bfloat16* ql = QL + ((size_t)bh * NN + m0) * DD;
    const __nv_bfloat16* kh = KH + ((size_t)bh * NN + n0) * DD;
    const __nv_bfloat16* kl = KL + ((size_t)bh * NN + n0) * DD;
#pragma unroll
    for (int rep = 0; rep < 4; ++rep) {
        int idx = t + rep * 256;
        int r = idx >> 3, c8 = idx & 7;
        uint32_t off = sw128(r * 128 + c8 * 16);
        int go = r * DD + c8 * 8;
        *(uint4*)(smem + DK_AH + off) = *(const uint4*)(qh + go);
        *(uint4*)(smem + DK_AL + off) = *(const uint4*)(ql + go);
        *(uint4*)(smem + DK_BH + off) = *(const uint4*)(kh + go);
        *(uint4*)(smem + DK_BL + off) = *(const uint4*)(kl + go);
    }
    __syncthreads();

    float acc[2][8][4] = {};
    const uint32_t aoffs[3] = {DK_AH, DK_AH, DK_AL};
    const uint32_t boffs[3] = {DK_BH, DK_BL, DK_BH};
#pragma unroll
    for (int c3 = 0; c3 < 3; ++c3) {
        const uint32_t abase = sb + aoffs[c3];
        const uint32_t bbase = sb + boffs[c3];
#pragma unroll
        for (int ks = 0; ks < 4; ++ks) {
            uint32_t a[2][4];
#pragma unroll
            for (int mt = 0; mt < 2; ++mt) {
                uint32_t row = wm + mt * 16 + (lane & 15);
                ldsm4(a[mt], abase + sw128(row * 128 + ks * 32 + (lane >> 4) * 16));
            }
            uint32_t bf[4][4];
#pragma unroll
            for (int np = 0; np < 4; ++np) {
                uint32_t row = wn + np * 16 + (lane & 7) + ((lane >> 4) << 3);
                ldsm4(bf[np], bbase + sw128(row * 128 + ks * 32 + ((lane >> 3) & 1) * 16));
            }
#pragma unroll
            for (int mt = 0; mt < 2; ++mt)
#pragma unroll
                for (int nt = 0; nt < 8; ++nt)
                    mma16816(acc[mt][nt], a[mt], bf[nt >> 1][(nt & 1) * 2], bf[nt >> 1][(nt & 1) * 2 + 1]);
        }
    }

    float* C = Dots + ((size_t)bh * NN + m0) * NN + n0;
#pragma unroll
    for (int mt = 0; mt < 2; ++mt) {
        int row = wm + mt * 16 + (lane >> 2);
#pragma unroll
        for (int nt = 0; nt < 8; ++nt) {
            int col = wn + nt * 8 + (lane & 3) * 2;
            *(float2*)(C + (size_t)row * NN + col)       = make_float2(acc[mt][nt][0], acc[mt][nt][1]);
            *(float2*)(C + (size_t)(row + 8) * NN + col) = make_float2(acc[mt][nt][2], acc[mt][nt][3]);
        }
    }
}

// ---------------- K3: fused pre-mix + pos + mask + softmax + post-mix --------
// 512 threads, register-resident (4 cols x 8 heads per thread)
__global__ __launch_bounds__(512)
void mix_softmax_kernel(const float* __restrict__ Dots,
                        const float* __restrict__ Pos,
                        const unsigned char* __restrict__ Mask,
                        const float* __restrict__ Wpre,
                        const float* __restrict__ Bpre,
                        const float* __restrict__ Wpost,
                        const float* __restrict__ Bpost,
                        __nv_bfloat16* __restrict__ AttnHi,
                        __nv_bfloat16* __restrict__ AttnLo)
{
    __shared__ float wpre_s[64], wpost_s[64], bpre_s[8], bpost_s[8];
    __shared__ float red[8][16];
    __shared__ float gstat[8];
    const int b = blockIdx.x;    // x-major: b=0,1 of same i adjacent -> pos L2 reuse
    const int i = blockIdx.y;
    const int t = threadIdx.x;
    const int lane = t & 31, warp = t >> 5;
    if (t < 64) { wpre_s[t] = Wpre[t]; wpost_s[t] = Wpost[t]; }
    if (t >= 64 && t < 72) { bpre_s[t - 64] = Bpre[t - 64]; bpost_s[t - 64] = Bpost[t - 64]; }
    __syncthreads();

    const unsigned char* mrow = Mask + ((size_t)b * NN + i) * NN;
    float v[4][8];
    float lmax[8];
#pragma unroll
    for (int g = 0; g < 8; ++g) lmax[g] = -FLT_MAX;

#pragma unroll
    for (int c = 0; c < 4; ++c) {
        int j = t + c * 512;
        float sv[8];
#pragma unroll
        for (int h = 0; h < 8; ++h)
            sv[h] = Dots[(((size_t)b * HH + h) * NN + i) * NN + j];
        bool mk = mrow[j] != 0;
#pragma unroll
        for (int g = 0; g < 8; ++g) {
            float val = bpre_s[g];
#pragma unroll
            for (int h = 0; h < 8; ++h) val = fmaf(wpre_s[g * 8 + h], sv[h], val);
            val += Pos[((size_t)g * NN + i) * NN + j];
            if (mk) val = -FLT_MAX;
            v[c][g] = val;
            lmax[g] = fmaxf(lmax[g], val);
        }
    }
    // block max per g over 16 warps
#pragma unroll
    for (int g = 0; g < 8; ++g) {
        float m = lmax[g];
#pragma unroll
        for (int o = 16; o > 0; o >>= 1) m = fmaxf(m, __shfl_xor_sync(0xffffffffu, m, o));
        if (lane == 0) red[g][warp] = m;
    }
    __syncthreads();
    if (t < 8) {
        float m = red[t][0];
#pragma unroll
        for (int w = 1; w < 16; ++w) m = fmaxf(m, red[t][w]);
        gstat[t] = m;
    }
    __syncthreads();
    float gmaxr[8];
#pragma unroll
    for (int g = 0; g < 8; ++g) gmaxr[g] = gstat[g];

    float lsum[8] = {};
#pragma unroll
    for (int c = 0; c < 4; ++c)
#pragma unroll
        for (int g = 0; g < 8; ++g) {
            float e = __expf(v[c][g] - gmaxr[g]);
            v[c][g] = e;
            lsum[g] += e;
        }
#pragma unroll
    for (int g = 0; g < 8; ++g) {
        float s = lsum[g];
#pragma unroll
        for (int o = 16; o > 0; o >>= 1) s += __shfl_xor_sync(0xffffffffu, s, o);
        if (lane == 0) red[g][warp] = s;
    }
    __syncthreads();
    if (t < 8) {
        float s = 0.f;
#pragma unroll
        for (int w = 0; w < 16; ++w) s += red[t][w];
        gstat[t] = 1.0f / s;
    }
    __syncthreads();
    float inv[8];
#pragma unroll
    for (int h = 0; h < 8; ++h) inv[h] = gstat[h];

#pragma unroll
    for (int c = 0; c < 4; ++c) {
        int j = t + c * 512;
        float p[8];
#pragma unroll
        for (int h = 0; h < 8; ++h) p[h] = v[c][h] * inv[h];
#pragma unroll
        for (int g = 0; g < 8; ++g) {
            float o = bpost_s[g];
#pragma unroll
            for (int h = 0; h < 8; ++h) o = fmaf(wpost_s[g * 8 + h], p[h], o);
            size_t ofs = (((size_t)b * HH + g) * NN + i) * NN + j;
            __nv_bfloat16 hi = __float2bfloat16(o);
            AttnHi[ofs] = hi;
            AttnLo[ofs] = __float2bfloat16(o - __bfloat162float(hi));
        }
    }
}

// ---------------- K4: out = attn @ v via mma.sync ----------------------------
#define AV_AH 0
#define AV_AL 16384
#define AV_BH 32768
#define AV_BL 40960
#define AV_SMEM 49152

__global__ __launch_bounds__(256)
void av_mma_kernel(const __nv_bfloat16* __restrict__ AttnHi, const __nv_bfloat16* __restrict__ AttnLo,
                   const __nv_bfloat16* __restrict__ VTH, const __nv_bfloat16* __restrict__ VTL,
                   __nv_bfloat16* __restrict__ OutH, __nv_bfloat16* __restrict__ OutL)
{
    extern __shared__ __align__(128) char smem[];
    const uint32_t sb = smem_u32(smem);
    const int t = threadIdx.x;
    const int lane = t & 31, warp = t >> 5;
    const int wm = (warp & 3) * 32;
    const int wn = (warp >> 2) * 32;
    const int bh = blockIdx.y;
    const int b = bh >> 3, h = bh & 7;
    const int m0 = blockIdx.x * 128;

    const __nv_bfloat16* Ah = AttnHi + ((size_t)bh * NN + m0) * NN;
    const __nv_bfloat16* Al = AttnLo + ((size_t)bh * NN + m0) * NN;
    const __nv_bfloat16* Vh = VTH + (size_t)bh * DD * NN;
    const __nv_bfloat16* Vl = VTL + (size_t)bh * DD * NN;

    float acc[2][4][4] = {};
    const uint32_t aoffs[3] = {AV_AH, AV_AH, AV_AL};
    const uint32_t boffs[3] = {AV_BH, AV_BL, AV_BH};

    for (int it = 0; it < 32; ++it) {
        const int j0 = it * 64;
#pragma unroll
        for (int rep = 0; rep < 4; ++rep) {
            int idx = t + rep * 256;
            int r = idx >> 3, c8 = idx & 7;
            uint32_t off = sw128(r * 128 + c8 * 16);
            size_t go = (size_t)r * NN + j0 + c8 * 8;
            *(uint4*)(smem + AV_AH + off) = *(const uint4*)(Ah + go);
            *(uint4*)(smem + AV_AL + off) = *(const uint4*)(Al + go);
        }
#pragma unroll
        for (int rep = 0; rep < 2; ++rep) {
            int idx = t + rep * 256;
            int r = idx >> 3, c8 = idx & 7;
            uint32_t off = sw128(r * 128 + c8 * 16);
            size_t go = (size_t)r * NN + j0 + c8 * 8;
            *(uint4*)(smem + AV_BH + off) = *(const uint4*)(Vh + go);
            *(uint4*)(smem + AV_BL + off) = *(const uint4*)(Vl + go);
        }
        __syncthreads();
#pragma unroll
        for (int c3 = 0; c3 < 3; ++c3) {
            const uint32_t abase = sb + aoffs[c3];
            const uint32_t bbase = sb + boffs[c3];
#pragma unroll
            for (int ks = 0; ks < 4; ++ks) {
                uint32_t a[2][4];
#pragma unroll
                for (int mt = 0; mt < 2; ++mt) {
                    uint32_t row = wm + mt * 16 + (lane & 15);
                    ldsm4(a[mt], abase + sw128(row * 128 + ks * 32 + (lane >> 4) * 16));
                }
                uint32_t bf[2][4];
#pragma unroll
                for (int np = 0; np < 2; ++np) {
                    uint32_t row = wn + np * 16 + (lane & 7) + ((lane >> 4) << 3);
                    ldsm4(bf[np], bbase + sw128(row * 128 + ks * 32 + ((lane >> 3) & 1) * 16));
                }
#pragma unroll
                for (int mt = 0; mt < 2; ++mt)
#pragma unroll
                    for (int nt = 0; nt < 4; ++nt)
                        mma16816(acc[mt][nt], a[mt], bf[nt >> 1][(nt & 1) * 2], bf[nt >> 1][(nt & 1) * 2 + 1]);
            }
        }
        __syncthreads();
    }

    // epilogue: write outf hi/lo bf16 at [b][i][h*64+d]
#pragma unroll
    for (int mt = 0; mt < 2; ++mt) {
        int row = m0 + wm + mt * 16 + (lane >> 2);
#pragma unroll
        for (int half = 0; half < 2; ++half) {
            size_t rb = ((size_t)b * NN + row + half * 8) * (HH * DD) + h * DD;
#pragma unroll
            for (int nt = 0; nt < 4; ++nt) {
                int col = wn + nt * 8 + (lane & 3) * 2;
                float v0 = acc[mt][nt][half * 2 + 0];
                float v1 = acc[mt][nt][half * 2 + 1];
                __nv_bfloat16 h0 = __float2bfloat16(v0);
                __nv_bfloat16 h1 = __float2bfloat16(v1);
                __nv_bfloat162 hp; hp.x = h0; hp.y = h1;
                __nv_bfloat162 lp;
                lp.x = __float2bfloat16(v0 - __bfloat162float(h0));
                lp.y = __float2bfloat16(v1 - __bfloat162float(h1));
                *(__nv_bfloat162*)(OutH + rb + col) = hp;
                *(__nv_bfloat162*)(OutL + rb + col) = lp;
            }
        }
    }
}

// ---------------- K5: final projection y = outf @ Wout^T (split-bf16 MMA) ----
__global__ __launch_bounds__(256)
void out_mma_kernel(const __nv_bfloat16* __restrict__ OH, const __nv_bfloat16* __restrict__ OL,
                    const __nv_bfloat16* __restrict__ WH, const __nv_bfloat16* __restrict__ WL,
                    float* __restrict__ Y)
{
    extern __shared__ __align__(128) char smem[];
    const uint32_t sb = smem_u32(smem);
    const int m0 = blockIdx.y * 128;
    const int n0 = blockIdx.x * 128;
    const int lane = threadIdx.x & 31, warp = threadIdx.x >> 5;
    const int wm = (warp & 3) * 32, wn = (warp >> 2) * 64;
    float acc[2][8][4] = {};
    mma_nt_mainloop(OH, OL, HH * DD, m0, WH, WL, HH * DD, n0, HH * DD, smem, sb, acc);

#pragma unroll
    for (int mt = 0; mt < 2; ++mt) {
        int row = m0 + wm + mt * 16 + (lane >> 2);
#pragma unroll
        for (int nt = 0; nt < 8; ++nt) {
            int col = n0 + wn + nt * 8 + (lane & 3) * 2;
            *(float2*)(Y + (size_t)row * CC + col)       = make_float2(acc[mt][nt][0], acc[mt][nt][1]);
            *(float2*)(Y + (size_t)(row + 8) * CC + col) = make_float2(acc[mt][nt][2], acc[mt][nt][3]);
        }
    }
}

// ---------------- launch -----------------------------------------------------
extern "C" void kernel_launch(void* const* d_in, const int* in_sizes, int n_in,
                              void* d_out, int out_size)
{
    (void)in_sizes; (void)n_in; (void)out_size;
    const float*         x     = (const float*)d_in[0];
    const float*         pos   = (const float*)d_in[1];
    const unsigned char* mask  = (const unsigned char*)d_in[2];
    const float*         Wqkv  = (const float*)d_in[3];
    const float*         Wout  = (const float*)d_in[4];
    const float*         Wpre  = (const float*)d_in[5];
    const float*         bpre  = (const float*)d_in[6];
    const float*         Wpost = (const float*)d_in[7];
    const float*         bpost = (const float*)d_in[8];
    float* y = (float*)d_out;

    float *v, *dots;
    __nv_bfloat16 *xh, *xl, *wqh, *wql, *woh, *wol;
    __nv_bfloat16 *qh, *ql, *kh, *kl, *vth, *vtl, *ah, *al, *oh, *ol;
    cudaGetSymbolAddress((void**)&v,    g_v);
    cudaGetSymbolAddress((void**)&dots, g_dots);
    cudaGetSymbolAddress((void**)&xh,  g_xh);
    cudaGetSymbolAddress((void**)&xl,  g_xl);
    cudaGetSymbolAddress((void**)&wqh, g_wqh);
    cudaGetSymbolAddress((void**)&wql, g_wql);
    cudaGetSymbolAddress((void**)&woh, g_woh);
    cudaGetSymbolAddress((void**)&wol, g_wol);
    cudaGetSymbolAddress((void**)&qh,  g_qs_hi);
    cudaGetSymbolAddress((void**)&ql,  g_qs_lo);
    cudaGetSymbolAddress((void**)&kh,  g_ks_hi);
    cudaGetSymbolAddress((void**)&kl,  g_ks_lo);
    cudaGetSymbolAddress((void**)&vth, g_vt_hi);
    cudaGetSymbolAddress((void**)&vtl, g_vt_lo);
    cudaGetSymbolAddress((void**)&ah,  g_attn_hi);
    cudaGetSymbolAddress((void**)&al,  g_attn_lo);
    cudaGetSymbolAddress((void**)&oh,  g_outf_hi);
    cudaGetSymbolAddress((void**)&ol,  g_outf_lo);

    cudaFuncSetAttribute(qkv_mma_kernel,  cudaFuncAttributeMaxDynamicSharedMemorySize, GK_SMEM);
    cudaFuncSetAttribute(out_mma_kernel,  cudaFuncAttributeMaxDynamicSharedMemorySize, GK_SMEM);
    cudaFuncSetAttribute(dots_mma_kernel, cudaFuncAttributeMaxDynamicSharedMemorySize, DK_SMEM);
    cudaFuncSetAttribute(av_mma_kernel,   cudaFuncAttributeMaxDynamicSharedMemorySize, AV_SMEM);

    split_kernel<<<(BB * NN * CC + 255) / 256, 256>>>(x, xh, xl, BB * NN * CC);
    split_kernel<<<(FF * CC + 255) / 256, 256>>>(Wqkv, wqh, wql, FF * CC);
    split_kernel<<<(CC * HH * DD + 255) / 256, 256>>>(Wout, woh, wol, CC * HH * DD);

    qkv_mma_kernel<<<dim3(FF / 128, (BB * NN) / 128), 256, GK_SMEM>>>(xh, xl, wqh, wql,
                                                                      qh, ql, kh, kl, v);
    convert_v_kernel<<<dim3(NN / 64, BB * HH), 256>>>(v, vth, vtl);
    dots_mma_kernel<<<dim3(NN / 128, NN / 128, BB * HH), 256, DK_SMEM>>>(qh, ql, kh, kl, dots);
    mix_softmax_kernel<<<dim3(BB, NN), 512>>>(dots, pos, mask, Wpre, bpre, Wpost, bpost, ah, al);
    av_mma_kernel<<<dim3(NN / 128, BB * HH), 256, AV_SMEM>>>(ah, al, vth, vtl, oh, ol);
    out_mma_kernel<<<dim3(CC / 128, (BB * NN) / 128), 256, GK_SMEM>>>(oh, ol, woh, wol, y);
}

// round 6
// speedup vs baseline: 1.9183x; 1.2015x over previous
#include <cuda_runtime.h>
#include <cuda_bf16.h>
#include <math.h>
#include <float.h>
#include <stdint.h>

// Problem constants
#define BB 2
#define NN 2048
#define CC 512
#define HH 8
#define DD 64
#define FF 1536   // 3*H*D

// ==================== scratch (device globals) ====================
__device__ float g_v[BB * HH * NN * DD];
__device__ float g_dots[(size_t)BB * HH * NN * NN];            // 256 MiB
__device__ __align__(256) __nv_bfloat16 g_xh[BB * NN * CC];
__device__ __align__(256) __nv_bfloat16 g_xl[BB * NN * CC];
__device__ __align__(256) __nv_bfloat16 g_wqh[FF * CC];
__device__ __align__(256) __nv_bfloat16 g_wql[FF * CC];
__device__ __align__(256) __nv_bfloat16 g_woh[CC * HH * DD];
__device__ __align__(256) __nv_bfloat16 g_wol[CC * HH * DD];
__device__ __align__(256) __nv_bfloat16 g_qs_hi[BB * HH * NN * DD];
__device__ __align__(256) __nv_bfloat16 g_qs_lo[BB * HH * NN * DD];
__device__ __align__(256) __nv_bfloat16 g_ks_hi[BB * HH * NN * DD];
__device__ __align__(256) __nv_bfloat16 g_ks_lo[BB * HH * NN * DD];
__device__ __align__(256) __nv_bfloat16 g_vt_hi[BB * HH * DD * NN];   // [bh][d][n]
__device__ __align__(256) __nv_bfloat16 g_vt_lo[BB * HH * DD * NN];
__device__ __align__(256) __nv_bfloat16 g_attn_hi[(size_t)BB * HH * NN * NN]; // 128 MiB
__device__ __align__(256) __nv_bfloat16 g_attn_lo[(size_t)BB * HH * NN * NN]; // 128 MiB
__device__ __align__(256) __nv_bfloat16 g_outf_hi[BB * NN * (HH * DD)];
__device__ __align__(256) __nv_bfloat16 g_outf_lo[BB * NN * (HH * DD)];

// ==================== helpers ====================
__device__ __forceinline__ uint32_t smem_u32(const void* p) {
    uint32_t a;
    asm("{ .reg .u64 t; cvta.to.shared.u64 t, %1; cvt.u32.u64 %0, t; }" : "=r"(a) : "l"(p));
    return a;
}
__device__ __forceinline__ uint32_t sw128(uint32_t off) { return off ^ ((off >> 3) & 0x70); }

__device__ __forceinline__ void ldsm4(uint32_t (&r)[4], uint32_t addr) {
    asm volatile("ldmatrix.sync.aligned.m8n8.x4.shared.b16 {%0,%1,%2,%3}, [%4];"
        : "=r"(r[0]), "=r"(r[1]), "=r"(r[2]), "=r"(r[3]) : "r"(addr));
}
__device__ __forceinline__ void mma16816(float (&c)[4], const uint32_t (&a)[4],
                                         uint32_t b0, uint32_t b1) {
    asm volatile("mma.sync.aligned.m16n8k16.row.col.f32.bf16.bf16.f32 "
        "{%0,%1,%2,%3}, {%4,%5,%6,%7}, {%8,%9}, {%0,%1,%2,%3};"
        : "+f"(c[0]), "+f"(c[1]), "+f"(c[2]), "+f"(c[3])
        : "r"(a[0]), "r"(a[1]), "r"(a[2]), "r"(a[3]), "r"(b0), "r"(b1));
}
__device__ __forceinline__ void cp16(uint32_t saddr, const void* gptr) {
    asm volatile("cp.async.cg.shared.global [%0], [%1], 16;" :: "r"(saddr), "l"(gptr));
}
#define CP_COMMIT() asm volatile("cp.async.commit_group;" ::: "memory")
__device__ __forceinline__ void cp_wait_dyn(int pend) {
    if (pend >= 2)      asm volatile("cp.async.wait_group 2;" ::: "memory");
    else if (pend == 1) asm volatile("cp.async.wait_group 1;" ::: "memory");
    else                asm volatile("cp.async.wait_group 0;" ::: "memory");
}

// ==================== pipelined split-bf16 NT MMA (128x128 tile, Kc=64) ======
// stage layout: AH 0 | AL 16K | BH 32K | BL 48K ; 3 stages x 64KB = 192KB
#define ST_AH 0
#define ST_AL 16384
#define ST_BH 32768
#define ST_BL 49152
#define ST_STRIDE 65536
#define GK_SMEM (3 * ST_STRIDE)

__device__ __forceinline__ void load_stage_nt(
    uint32_t st, const __nv_bfloat16* __restrict__ AH, const __nv_bfloat16* __restrict__ AL,
    int lda, int m0, const __nv_bfloat16* __restrict__ BH, const __nv_bfloat16* __restrict__ BL,
    int ldb, int n0, int k0)
{
    const int t = threadIdx.x;
#pragma unroll
    for (int rep = 0; rep < 4; ++rep) {
        int idx = t + rep * 256;
        int r = idx >> 3, c8 = idx & 7;
        uint32_t off = sw128(r * 128 + c8 * 16);
        size_t ga = (size_t)(m0 + r) * lda + k0 + c8 * 8;
        size_t gb = (size_t)(n0 + r) * ldb + k0 + c8 * 8;
        cp16(st + ST_AH + off, AH + ga);
        cp16(st + ST_AL + off, AL + ga);
        cp16(st + ST_BH + off, BH + gb);
        cp16(st + ST_BL + off, BL + gb);
    }
}

__device__ __forceinline__ void compute_stage_128(uint32_t st, float (&acc)[2][8][4],
                                                  int lane, int wm, int wn)
{
#pragma unroll
    for (int ks = 0; ks < 4; ++ks) {
        uint32_t aH[2][4], aL[2][4];
#pragma unroll
        for (int mt = 0; mt < 2; ++mt) {
            uint32_t row = wm + mt * 16 + (lane & 15);
            uint32_t so = sw128(row * 128 + ks * 32 + (lane >> 4) * 16);
            ldsm4(aH[mt], st + ST_AH + so);
            ldsm4(aL[mt], st + ST_AL + so);
        }
        uint32_t bH[4][4], bL[4][4];
#pragma unroll
        for (int np = 0; np < 4; ++np) {
            uint32_t row = wn + np * 16 + (lane & 7) + ((lane >> 4) << 3);
            uint32_t so = sw128(row * 128 + ks * 32 + ((lane >> 3) & 1) * 16);
            ldsm4(bH[np], st + ST_BH + so);
            ldsm4(bL[np], st + ST_BL + so);
        }
#pragma unroll
        for (int mt = 0; mt < 2; ++mt)
#pragma unroll
            for (int nt = 0; nt < 8; ++nt) {
                uint32_t b0h = bH[nt >> 1][(nt & 1) * 2], b1h = bH[nt >> 1][(nt & 1) * 2 + 1];
                uint32_t b0l = bL[nt >> 1][(nt & 1) * 2], b1l = bL[nt >> 1][(nt & 1) * 2 + 1];
                mma16816(acc[mt][nt], aH[mt], b0h, b1h);
                mma16816(acc[mt][nt], aH[mt], b0l, b1l);
                mma16816(acc[mt][nt], aL[mt], b0h, b1h);
            }
    }
}

__device__ __forceinline__ void mma_nt_pipelined(
    const __nv_bfloat16* __restrict__ AH, const __nv_bfloat16* __restrict__ AL, int lda, int m0,
    const __nv_bfloat16* __restrict__ BH, const __nv_bfloat16* __restrict__ BL, int ldb, int n0,
    int K, uint32_t sb, float (&acc)[2][8][4], int lane, int wm, int wn)
{
    const int nk = K / 64;
    load_stage_nt(sb, AH, AL, lda, m0, BH, BL, ldb, n0, 0);
    CP_COMMIT();
    if (nk > 1) {
        load_stage_nt(sb + ST_STRIDE, AH, AL, lda, m0, BH, BL, ldb, n0, 64);
        CP_COMMIT();
    }
    for (int kc = 0; kc < nk; ++kc) {
        if (kc + 2 < nk) {
            load_stage_nt(sb + ((kc + 2) % 3) * ST_STRIDE, AH, AL, lda, m0, BH, BL, ldb, n0,
                          (kc + 2) * 64);
            CP_COMMIT();
        }
        int pend = (nk < kc + 3 ? nk : kc + 3) - (kc + 1);
        cp_wait_dyn(pend);
        __syncthreads();
        compute_stage_128(sb + (kc % 3) * ST_STRIDE, acc, lane, wm, wn);
        __syncthreads();
    }
}

// ---------------- K0: split fp32 -> bf16 hi/lo ----------------
__global__ void split_kernel(const float* __restrict__ in, __nv_bfloat16* __restrict__ hi,
                             __nv_bfloat16* __restrict__ lo, int n)
{
    int i = blockIdx.x * 256 + threadIdx.x;
    if (i < n) {
        float v = in[i];
        __nv_bfloat16 h = __float2bfloat16(v);
        hi[i] = h;
        lo[i] = __float2bfloat16(v - __bfloat162float(h));
    }
}

// ---------------- K1: QKV projection (pipelined MMA) + scatter ---------------
__global__ __launch_bounds__(256)
void qkv_mma_kernel(const __nv_bfloat16* __restrict__ XH, const __nv_bfloat16* __restrict__ XL,
                    const __nv_bfloat16* __restrict__ WH, const __nv_bfloat16* __restrict__ WL,
                    __nv_bfloat16* __restrict__ QH, __nv_bfloat16* __restrict__ QL,
                    __nv_bfloat16* __restrict__ KH, __nv_bfloat16* __restrict__ KL,
                    float* __restrict__ V)
{
    extern __shared__ __align__(128) char smem[];
    const uint32_t sb = smem_u32(smem);
    const int m0 = blockIdx.y * 128;
    const int n0 = blockIdx.x * 128;
    const int lane = threadIdx.x & 31, warp = threadIdx.x >> 5;
    const int wm = (warp & 3) * 32, wn = (warp >> 2) * 64;
    float acc[2][8][4] = {};
    mma_nt_pipelined(XH, XL, CC, m0, WH, WL, CC, n0, CC, sb, acc, lane, wm, wn);

#pragma unroll
    for (int mt = 0; mt < 2; ++mt) {
        int row0 = m0 + wm + mt * 16 + (lane >> 2);
#pragma unroll
        for (int half = 0; half < 2; ++half) {
            int m = row0 + half * 8;
            int b = m >> 11, n = m & 2047;
#pragma unroll
            for (int nt = 0; nt < 8; ++nt) {
                int f0 = n0 + wn + nt * 8 + (lane & 3) * 2;
#pragma unroll
                for (int e = 0; e < 2; ++e) {
                    int f = f0 + e;
                    float val = acc[mt][nt][half * 2 + e];
                    int h = f / 192;
                    int r = f - h * 192;
                    int d = r / 3;
                    int s = r - d * 3;
                    size_t idx = (((size_t)b * HH + h) * NN + n) * DD + d;
                    if (s == 0) {
                        float qv = val * 0.125f;
                        __nv_bfloat16 hb = __float2bfloat16(qv);
                        QH[idx] = hb;
                        QL[idx] = __float2bfloat16(qv - __bfloat162float(hb));
                    } else if (s == 1) {
                        __nv_bfloat16 hb = __float2bfloat16(val);
                        KH[idx] = hb;
                        KL[idx] = __float2bfloat16(val - __bfloat162float(hb));
                    } else {
                        V[idx] = val;
                    }
                }
            }
        }
    }
}

// ---------------- K1b: transpose V -> vt hi/lo -------------------------------
__global__ void convert_v_kernel(const float* __restrict__ V,
                                 __nv_bfloat16* __restrict__ VTH, __nv_bfloat16* __restrict__ VTL)
{
    __shared__ float ts[64][65];
    const int bh = blockIdx.y;
    const int n0 = blockIdx.x * 64;
    const int t = threadIdx.x;
    const size_t base = ((size_t)bh * NN + n0) * DD;
    for (int idx = t; idx < 64 * 64; idx += 256)
        ts[idx >> 6][idx & 63] = V[base + idx];
    __syncthreads();
    for (int idx = t; idx < 64 * 64; idx += 256) {
        int d = idx >> 6, c = idx & 63;
        float vv = ts[c][d];
        __nv_bfloat16 vh = __float2bfloat16(vv);
        size_t o = ((size_t)bh * DD + d) * NN + n0 + c;
        VTH[o] = vh;
        VTL[o] = __float2bfloat16(vv - __bfloat162float(vh));
    }
}

// ---------------- K2: dots = (q_hi+lo)(k_hi+lo)^T via mma.sync --------------
#define DK_AH 0
#define DK_AL 16384
#define DK_BH 32768
#define DK_BL 49152
#define DK_SMEM 65536

__global__ __launch_bounds__(256)
void dots_mma_kernel(const __nv_bfloat16* __restrict__ QH, const __nv_bfloat16* __restrict__ QL,
                     const __nv_bfloat16* __restrict__ KH, const __nv_bfloat16* __restrict__ KL,
                     float* __restrict__ Dots)
{
    extern __shared__ __align__(128) char smem[];
    const uint32_t sb = smem_u32(smem);
    const int t = threadIdx.x;
    const int lane = t & 31, warp = t >> 5;
    const int wm = (warp & 3) * 32;
    const int wn = (warp >> 2) * 64;
    const int bh = blockIdx.z;
    const int m0 = blockIdx.y * 128;
    const int n0 = blockIdx.x * 128;

    const __nv_bfloat16* qh = QH + ((size_t)bh * NN + m0) * DD;
    const __nv_bfloat16* ql = QL + ((size_t)bh * NN + m0) * DD;
    const __nv_bfloat16* kh = KH + ((size_t)bh * NN + n0) * DD;
    const __nv_bfloat16* kl = KL + ((size_t)bh * NN + n0) * DD;
#pragma unroll
    for (int rep = 0; rep < 4; ++rep) {
        int idx = t + rep * 256;
        int r = idx >> 3, c8 = idx & 7;
        uint32_t off = sw128(r * 128 + c8 * 16);
        int go = r * DD + c8 * 8;
        cp16(sb + DK_AH + off, qh + go);
        cp16(sb + DK_AL + off, ql + go);
        cp16(sb + DK_BH + off, kh + go);
        cp16(sb + DK_BL + off, kl + go);
    }
    CP_COMMIT();
    asm volatile("cp.async.wait_group 0;" ::: "memory");
    __syncthreads();

    float acc[2][8][4] = {};
    compute_stage_128(sb, acc, lane, wm, wn);   // same ST_* layout as DK_*

    float* C = Dots + ((size_t)bh * NN + m0) * NN + n0;
#pragma unroll
    for (int mt = 0; mt < 2; ++mt) {
        int row = wm + mt * 16 + (lane >> 2);
#pragma unroll
        for (int nt = 0; nt < 8; ++nt) {
            int col = wn + nt * 8 + (lane & 3) * 2;
            *(float2*)(C + (size_t)row * NN + col)       = make_float2(acc[mt][nt][0], acc[mt][nt][1]);
            *(float2*)(C + (size_t)(row + 8) * NN + col) = make_float2(acc[mt][nt][2], acc[mt][nt][3]);
        }
    }
}

// ---------------- K3: fused pre-mix + pos + mask + softmax + post-mix --------
__global__ __launch_bounds__(512)
void mix_softmax_kernel(const float* __restrict__ Dots,
                        const float* __restrict__ Pos,
                        const unsigned char* __restrict__ Mask,
                        const float* __restrict__ Wpre,
                        const float* __restrict__ Bpre,
                        const float* __restrict__ Wpost,
                        const float* __restrict__ Bpost,
                        __nv_bfloat16* __restrict__ AttnHi,
                        __nv_bfloat16* __restrict__ AttnLo)
{
    __shared__ float wpre_s[64], wpost_s[64], bpre_s[8], bpost_s[8];
    __shared__ float red[8][16];
    __shared__ float gstat[8];
    const int b = blockIdx.x;
    const int i = blockIdx.y;
    const int t = threadIdx.x;
    const int lane = t & 31, warp = t >> 5;
    if (t < 64) { wpre_s[t] = Wpre[t]; wpost_s[t] = Wpost[t]; }
    if (t >= 64 && t < 72) { bpre_s[t - 64] = Bpre[t - 64]; bpost_s[t - 64] = Bpost[t - 64]; }
    __syncthreads();

    const unsigned char* mrow = Mask + ((size_t)b * NN + i) * NN;
    float v[4][8];
    float lmax[8];
#pragma unroll
    for (int g = 0; g < 8; ++g) lmax[g] = -FLT_MAX;

#pragma unroll
    for (int c = 0; c < 4; ++c) {
        int j = t + c * 512;
        float sv[8];
#pragma unroll
        for (int h = 0; h < 8; ++h)
            sv[h] = Dots[(((size_t)b * HH + h) * NN + i) * NN + j];
        bool mk = mrow[j] != 0;
#pragma unroll
        for (int g = 0; g < 8; ++g) {
            float val = bpre_s[g];
#pragma unroll
            for (int h = 0; h < 8; ++h) val = fmaf(wpre_s[g * 8 + h], sv[h], val);
            val += Pos[((size_t)g * NN + i) * NN + j];
            if (mk) val = -FLT_MAX;
            v[c][g] = val;
            lmax[g] = fmaxf(lmax[g], val);
        }
    }
#pragma unroll
    for (int g = 0; g < 8; ++g) {
        float m = lmax[g];
#pragma unroll
        for (int o = 16; o > 0; o >>= 1) m = fmaxf(m, __shfl_xor_sync(0xffffffffu, m, o));
        if (lane == 0) red[g][warp] = m;
    }
    __syncthreads();
    if (t < 8) {
        float m = red[t][0];
#pragma unroll
        for (int w = 1; w < 16; ++w) m = fmaxf(m, red[t][w]);
        gstat[t] = m;
    }
    __syncthreads();
    float gmaxr[8];
#pragma unroll
    for (int g = 0; g < 8; ++g) gmaxr[g] = gstat[g];

    float lsum[8] = {};
#pragma unroll
    for (int c = 0; c < 4; ++c)
#pragma unroll
        for (int g = 0; g < 8; ++g) {
            float e = __expf(v[c][g] - gmaxr[g]);
            v[c][g] = e;
            lsum[g] += e;
        }
#pragma unroll
    for (int g = 0; g < 8; ++g) {
        float s = lsum[g];
#pragma unroll
        for (int o = 16; o > 0; o >>= 1) s += __shfl_xor_sync(0xffffffffu, s, o);
        if (lane == 0) red[g][warp] = s;
    }
    __syncthreads();
    if (t < 8) {
        float s = 0.f;
#pragma unroll
        for (int w = 0; w < 16; ++w) s += red[t][w];
        gstat[t] = 1.0f / s;
    }
    __syncthreads();
    float inv[8];
#pragma unroll
    for (int h = 0; h < 8; ++h) inv[h] = gstat[h];

#pragma unroll
    for (int c = 0; c < 4; ++c) {
        int j = t + c * 512;
        float p[8];
#pragma unroll
        for (int h = 0; h < 8; ++h) p[h] = v[c][h] * inv[h];
#pragma unroll
        for (int g = 0; g < 8; ++g) {
            float o = bpost_s[g];
#pragma unroll
            for (int h = 0; h < 8; ++h) o = fmaf(wpost_s[g * 8 + h], p[h], o);
            size_t ofs = (((size_t)b * HH + g) * NN + i) * NN + j;
            __nv_bfloat16 hi = __float2bfloat16(o);
            AttnHi[ofs] = hi;
            AttnLo[ofs] = __float2bfloat16(o - __bfloat162float(hi));
        }
    }
}

// ---------------- K4: out = attn @ v (pipelined, 32 K-chunks) ----------------
// stage: AH 0 | AL 16K | BH 32K | BL 40K ; stride 48KB; 3 stages = 144KB
#define AV_AH 0
#define AV_AL 16384
#define AV_BH 32768
#define AV_BL 40960
#define AV_STRIDE 49152
#define AV_SMEM (3 * AV_STRIDE)

__device__ __forceinline__ void av_load_stage(uint32_t st,
    const __nv_bfloat16* __restrict__ Ah, const __nv_bfloat16* __restrict__ Al,
    const __nv_bfloat16* __restrict__ Vh, const __nv_bfloat16* __restrict__ Vl, int j0)
{
    const int t = threadIdx.x;
#pragma unroll
    for (int rep = 0; rep < 4; ++rep) {
        int idx = t + rep * 256;
        int r = idx >> 3, c8 = idx & 7;
        uint32_t off = sw128(r * 128 + c8 * 16);
        size_t go = (size_t)r * NN + j0 + c8 * 8;
        cp16(st + AV_AH + off, Ah + go);
        cp16(st + AV_AL + off, Al + go);
    }
#pragma unroll
    for (int rep = 0; rep < 2; ++rep) {
        int idx = t + rep * 256;
        int r = idx >> 3, c8 = idx & 7;
        uint32_t off = sw128(r * 128 + c8 * 16);
        size_t go = (size_t)r * NN + j0 + c8 * 8;
        cp16(st + AV_BH + off, Vh + go);
        cp16(st + AV_BL + off, Vl + go);
    }
}

__global__ __launch_bounds__(256)
void av_mma_kernel(const __nv_bfloat16* __restrict__ AttnHi, const __nv_bfloat16* __restrict__ AttnLo,
                   const __nv_bfloat16* __restrict__ VTH, const __nv_bfloat16* __restrict__ VTL,
                   __nv_bfloat16* __restrict__ OutH, __nv_bfloat16* __restrict__ OutL)
{
    extern __shared__ __align__(128) char smem[];
    const uint32_t sb = smem_u32(smem);
    const int t = threadIdx.x;
    const int lane = t & 31, warp = t >> 5;
    const int wm = (warp & 3) * 32;
    const int wn = (warp >> 2) * 32;
    const int bh = blockIdx.y;
    const int b = bh >> 3, h = bh & 7;
    const int m0 = blockIdx.x * 128;

    const __nv_bfloat16* Ah = AttnHi + ((size_t)bh * NN + m0) * NN;
    const __nv_bfloat16* Al = AttnLo + ((size_t)bh * NN + m0) * NN;
    const __nv_bfloat16* Vh = VTH + (size_t)bh * DD * NN;
    const __nv_bfloat16* Vl = VTL + (size_t)bh * DD * NN;

    float acc[2][4][4] = {};
    const int nk = 32;
    av_load_stage(sb, Ah, Al, Vh, Vl, 0); CP_COMMIT();
    av_load_stage(sb + AV_STRIDE, Ah, Al, Vh, Vl, 64); CP_COMMIT();

    for (int kc = 0; kc < nk; ++kc) {
        if (kc + 2 < nk) {
            av_load_stage(sb + ((kc + 2) % 3) * AV_STRIDE, Ah, Al, Vh, Vl, (kc + 2) * 64);
            CP_COMMIT();
        }
        int pend = (nk < kc + 3 ? nk : kc + 3) - (kc + 1);
        cp_wait_dyn(pend);
        __syncthreads();
        const uint32_t st = sb + (kc % 3) * AV_STRIDE;
#pragma unroll
        for (int ks = 0; ks < 4; ++ks) {
            uint32_t aH[2][4], aL[2][4];
#pragma unroll
            for (int mt = 0; mt < 2; ++mt) {
                uint32_t row = wm + mt * 16 + (lane & 15);
                uint32_t so = sw128(row * 128 + ks * 32 + (lane >> 4) * 16);
                ldsm4(aH[mt], st + AV_AH + so);
                ldsm4(aL[mt], st + AV_AL + so);
            }
            uint32_t bH[2][4], bL[2][4];
#pragma unroll
            for (int np = 0; np < 2; ++np) {
                uint32_t row = wn + np * 16 + (lane & 7) + ((lane >> 4) << 3);
                uint32_t so = sw128(row * 128 + ks * 32 + ((lane >> 3) & 1) * 16);
                ldsm4(bH[np], st + AV_BH + so);
                ldsm4(bL[np], st + AV_BL + so);
            }
#pragma unroll
            for (int mt = 0; mt < 2; ++mt)
#pragma unroll
                for (int nt = 0; nt < 4; ++nt) {
                    uint32_t b0h = bH[nt >> 1][(nt & 1) * 2], b1h = bH[nt >> 1][(nt & 1) * 2 + 1];
                    uint32_t b0l = bL[nt >> 1][(nt & 1) * 2], b1l = bL[nt >> 1][(nt & 1) * 2 + 1];
                    mma16816(acc[mt][nt], aH[mt], b0h, b1h);
                    mma16816(acc[mt][nt], aH[mt], b0l, b1l);
                    mma16816(acc[mt][nt], aL[mt], b0h, b1h);
                }
        }
        __syncthreads();
    }

#pragma unroll
    for (int mt = 0; mt < 2; ++mt) {
        int row = m0 + wm + mt * 16 + (lane >> 2);
#pragma unroll
        for (int half = 0; half < 2; ++half) {
            size_t rb = ((size_t)b * NN + row + half * 8) * (HH * DD) + h * DD;
#pragma unroll
            for (int nt = 0; nt < 4; ++nt) {
                int col = wn + nt * 8 + (lane & 3) * 2;
                float v0 = acc[mt][nt][half * 2 + 0];
                float v1 = acc[mt][nt][half * 2 + 1];
                __nv_bfloat16 h0 = __float2bfloat16(v0);
                __nv_bfloat16 h1 = __float2bfloat16(v1);
                __nv_bfloat162 hp; hp.x = h0; hp.y = h1;
                __nv_bfloat162 lp;
                lp.x = __float2bfloat16(v0 - __bfloat162float(h0));
                lp.y = __float2bfloat16(v1 - __bfloat162float(h1));
                *(__nv_bfloat162*)(OutH + rb + col) = hp;
                *(__nv_bfloat162*)(OutL + rb + col) = lp;
            }
        }
    }
}

// ---------------- K5: final projection y = outf @ Wout^T (pipelined MMA) -----
__global__ __launch_bounds__(256)
void out_mma_kernel(const __nv_bfloat16* __restrict__ OH, const __nv_bfloat16* __restrict__ OL,
                    const __nv_bfloat16* __restrict__ WH, const __nv_bfloat16* __restrict__ WL,
                    float* __restrict__ Y)
{
    extern __shared__ __align__(128) char smem[];
    const uint32_t sb = smem_u32(smem);
    const int m0 = blockIdx.y * 128;
    const int n0 = blockIdx.x * 128;
    const int lane = threadIdx.x & 31, warp = threadIdx.x >> 5;
    const int wm = (warp & 3) * 32, wn = (warp >> 2) * 64;
    float acc[2][8][4] = {};
    mma_nt_pipelined(OH, OL, HH * DD, m0, WH, WL, HH * DD, n0, HH * DD, sb, acc, lane, wm, wn);

#pragma unroll
    for (int mt = 0; mt < 2; ++mt) {
        int row = m0 + wm + mt * 16 + (lane >> 2);
#pragma unroll
        for (int nt = 0; nt < 8; ++nt) {
            int col = n0 + wn + nt * 8 + (lane & 3) * 2;
            *(float2*)(Y + (size_t)row * CC + col)       = make_float2(acc[mt][nt][0], acc[mt][nt][1]);
            *(float2*)(Y + (size_t)(row + 8) * CC + col) = make_float2(acc[mt][nt][2], acc[mt][nt][3]);
        }
    }
}

// ---------------- launch -----------------------------------------------------
extern "C" void kernel_launch(void* const* d_in, const int* in_sizes, int n_in,
                              void* d_out, int out_size)
{
    (void)in_sizes; (void)n_in; (void)out_size;
    const float*         x     = (const float*)d_in[0];
    const float*         pos   = (const float*)d_in[1];
    const unsigned char* mask  = (const unsigned char*)d_in[2];
    const float*         Wqkv  = (const float*)d_in[3];
    const float*         Wout  = (const float*)d_in[4];
    const float*         Wpre  = (const float*)d_in[5];
    const float*         bpre  = (const float*)d_in[6];
    const float*         Wpost = (const float*)d_in[7];
    const float*         bpost = (const float*)d_in[8];
    float* y = (float*)d_out;

    float *v, *dots;
    __nv_bfloat16 *xh, *xl, *wqh, *wql, *woh, *wol;
    __nv_bfloat16 *qh, *ql, *kh, *kl, *vth, *vtl, *ah, *al, *oh, *ol;
    cudaGetSymbolAddress((void**)&v,    g_v);
    cudaGetSymbolAddress((void**)&dots, g_dots);
    cudaGetSymbolAddress((void**)&xh,  g_xh);
    cudaGetSymbolAddress((void**)&xl,  g_xl);
    cudaGetSymbolAddress((void**)&wqh, g_wqh);
    cudaGetSymbolAddress((void**)&wql, g_wql);
    cudaGetSymbolAddress((void**)&woh, g_woh);
    cudaGetSymbolAddress((void**)&wol, g_wol);
    cudaGetSymbolAddress((void**)&qh,  g_qs_hi);
    cudaGetSymbolAddress((void**)&ql,  g_qs_lo);
    cudaGetSymbolAddress((void**)&kh,  g_ks_hi);
    cudaGetSymbolAddress((void**)&kl,  g_ks_lo);
    cudaGetSymbolAddress((void**)&vth, g_vt_hi);
    cudaGetSymbolAddress((void**)&vtl, g_vt_lo);
    cudaGetSymbolAddress((void**)&ah,  g_attn_hi);
    cudaGetSymbolAddress((void**)&al,  g_attn_lo);
    cudaGetSymbolAddress((void**)&oh,  g_outf_hi);
    cudaGetSymbolAddress((void**)&ol,  g_outf_lo);

    cudaFuncSetAttribute(qkv_mma_kernel,  cudaFuncAttributeMaxDynamicSharedMemorySize, GK_SMEM);
    cudaFuncSetAttribute(out_mma_kernel,  cudaFuncAttributeMaxDynamicSharedMemorySize, GK_SMEM);
    cudaFuncSetAttribute(dots_mma_kernel, cudaFuncAttributeMaxDynamicSharedMemorySize, DK_SMEM);
    cudaFuncSetAttribute(av_mma_kernel,   cudaFuncAttributeMaxDynamicSharedMemorySize, AV_SMEM);

    split_kernel<<<(BB * NN * CC + 255) / 256, 256>>>(x, xh, xl, BB * NN * CC);
    split_kernel<<<(FF * CC + 255) / 256, 256>>>(Wqkv, wqh, wql, FF * CC);
    split_kernel<<<(CC * HH * DD + 255) / 256, 256>>>(Wout, woh, wol, CC * HH * DD);

    qkv_mma_kernel<<<dim3(FF / 128, (BB * NN) / 128), 256, GK_SMEM>>>(xh, xl, wqh, wql,
                                                                      qh, ql, kh, kl, v);
    convert_v_kernel<<<dim3(NN / 64, BB * HH), 256>>>(v, vth, vtl);
    dots_mma_kernel<<<dim3(NN / 128, NN / 128, BB * HH), 256, DK_SMEM>>>(qh, ql, kh, kl, dots);
    mix_softmax_kernel<<<dim3(BB, NN), 512>>>(dots, pos, mask, Wpre, bpre, Wpost, bpost, ah, al);
    av_mma_kernel<<<dim3(NN / 128, BB * HH), 256, AV_SMEM>>>(ah, al, vth, vtl, oh, ol);
    out_mma_kernel<<<dim3(CC / 128, (BB * NN) / 128), 256, GK_SMEM>>>(oh, ol, woh, wol, y);
}